// round 4
// baseline (speedup 1.0000x reference)
#include <cuda_runtime.h>
#include <math.h>

#define NB   8
#define SEQ  2048
#define HD   128
#define BM   32
#define BN   64
#define NTH  256
#define KSTR (HD + 4)   /* 132 floats: bank-conflict-free row stride for K/V */
#define PSTR (BN + 4)   /* 68 floats */
#define NEGV (-1.0e9f)

// Dynamic smem layout (floats):
//   sQ : BM*HD          (scaled Q tile)
//   sK : BN*KSTR
//   sV : BN*KSTR
//   sP : BM*PSTR        (probability tile; reused as scratch for mean-of-V)
#define SMEM_FLOATS (BM*HD + 2*BN*KSTR + BM*PSTR)

__global__ __launch_bounds__(NTH, 2)
void attn_kernel(const float* __restrict__ Q, const float* __restrict__ K,
                 const float* __restrict__ V, const int* __restrict__ LENS,
                 float* __restrict__ OUT)
{
    extern __shared__ float sm[];
    float* sQ = sm;
    float* sK = sQ + BM * HD;
    float* sV = sK + BN * KSTR;
    float* sP = sV + BN * KSTR;

    const int b   = blockIdx.y;
    const int q0  = blockIdx.x * BM;
    const int len = LENS[b];
    const int tid = threadIdx.x;
    const int ty  = tid >> 5;   // warp id 0..7  -> rows {ty, ty+8, ty+16, ty+24}
    const int tx  = tid & 31;   // lane          -> score cols {tx, tx+32}, out cols {4tx..4tx+3}

    const float* qb = Q + ((long)b * SEQ + q0) * HD;
    const float* kb = K + (long)b * SEQ * HD;
    const float* vb = V + (long)b * SEQ * HD;
    float*       ob = OUT + ((long)b * SEQ + q0) * HD;

    const bool any_attn = (q0 < len);
    const bool any_mean = (q0 + BM > len);   // covers len==0 too

    if (any_attn) {
        // ---- load Q tile (pre-scaled by 1/sqrt(HD)) ----
        const float scale = 0.088388347648318447f;  // 1/sqrt(128)
        for (int idx = tid * 4; idx < BM * HD; idx += NTH * 4) {
            float4 t = *(const float4*)(qb + idx);
            t.x *= scale; t.y *= scale; t.z *= scale; t.w *= scale;
            *(float4*)(sQ + idx) = t;
        }

        float acc[4][4];
        float mrow[4], lrow[4];
        #pragma unroll
        for (int i = 0; i < 4; i++) {
            mrow[i] = -INFINITY; lrow[i] = 0.f;
            acc[i][0] = acc[i][1] = acc[i][2] = acc[i][3] = 0.f;
        }

        const int nkt = (len + BN - 1) / BN;
        for (int kt = 0; kt < nkt; kt++) {
            __syncthreads();   // prior PV reads of sV done before overwrite
            // ---- stage K,V tiles ----
            const float* kbt = kb + (long)kt * BN * HD;
            const float* vbt = vb + (long)kt * BN * HD;
            for (int idx = tid * 4; idx < BN * HD; idx += NTH * 4) {
                int r = idx >> 7, c = idx & (HD - 1);
                *(float4*)(sK + r * KSTR + c) = *(const float4*)(kbt + idx);
                *(float4*)(sV + r * KSTR + c) = *(const float4*)(vbt + idx);
            }
            __syncthreads();

            // ---- scores: 4 rows x 2 cols per thread ----
            float s0a[4] = {0.f,0.f,0.f,0.f};
            float s1a[4] = {0.f,0.f,0.f,0.f};
            #pragma unroll 8
            for (int d = 0; d < HD; d += 4) {
                float4 k0 = *(const float4*)(sK + tx * KSTR + d);
                float4 k1 = *(const float4*)(sK + (tx + 32) * KSTR + d);
                #pragma unroll
                for (int i = 0; i < 4; i++) {
                    float4 qv = *(const float4*)(sQ + (ty + 8 * i) * HD + d); // warp-broadcast
                    s0a[i] += qv.x*k0.x + qv.y*k0.y + qv.z*k0.z + qv.w*k0.w;
                    s1a[i] += qv.x*k1.x + qv.y*k1.y + qv.z*k1.z + qv.w*k1.w;
                }
            }

            // ---- key mask (only the last tile can be partial) ----
            const int kc0 = kt * BN + tx;
            if (kc0 >= len)      { s0a[0]=s0a[1]=s0a[2]=s0a[3]=NEGV; }
            if (kc0 + 32 >= len) { s1a[0]=s1a[1]=s1a[2]=s1a[3]=NEGV; }

            // ---- online softmax (rows are warp-uniform -> full-warp reduce) ----
            #pragma unroll
            for (int i = 0; i < 4; i++) {
                float tm = fmaxf(s0a[i], s1a[i]);
                #pragma unroll
                for (int off = 16; off > 0; off >>= 1)
                    tm = fmaxf(tm, __shfl_xor_sync(0xffffffffu, tm, off));
                float mnew  = fmaxf(mrow[i], tm);
                float alpha = __expf(mrow[i] - mnew);   // exp(-inf)=0 on first tile
                mrow[i] = mnew;
                float p0 = __expf(s0a[i] - mnew);       // masked -> exp(~-1e9)=0 exactly
                float p1 = __expf(s1a[i] - mnew);
                float rs = p0 + p1;
                #pragma unroll
                for (int off = 16; off > 0; off >>= 1)
                    rs += __shfl_xor_sync(0xffffffffu, rs, off);
                lrow[i] = lrow[i] * alpha + rs;
                acc[i][0] *= alpha; acc[i][1] *= alpha;
                acc[i][2] *= alpha; acc[i][3] *= alpha;
                sP[(ty + 8 * i) * PSTR + tx]      = p0;
                sP[(ty + 8 * i) * PSTR + tx + 32] = p1;
            }
            __syncthreads();

            // ---- O += P @ V : each thread 4 rows x 4 contiguous cols (4tx..4tx+3) ----
            #pragma unroll 4
            for (int kk = 0; kk < BN; kk += 4) {
                float4 v0 = *(const float4*)(sV + (kk + 0) * KSTR + 4 * tx);
                float4 v1 = *(const float4*)(sV + (kk + 1) * KSTR + 4 * tx);
                float4 v2 = *(const float4*)(sV + (kk + 2) * KSTR + 4 * tx);
                float4 v3 = *(const float4*)(sV + (kk + 3) * KSTR + 4 * tx);
                #pragma unroll
                for (int i = 0; i < 4; i++) {
                    float4 pp = *(const float4*)(sP + (ty + 8 * i) * PSTR + kk); // broadcast
                    acc[i][0] += pp.x*v0.x + pp.y*v1.x + pp.z*v2.x + pp.w*v3.x;
                    acc[i][1] += pp.x*v0.y + pp.y*v1.y + pp.z*v2.y + pp.w*v3.y;
                    acc[i][2] += pp.x*v0.z + pp.y*v1.z + pp.z*v2.z + pp.w*v3.z;
                    acc[i][3] += pp.x*v0.w + pp.y*v1.w + pp.z*v2.w + pp.w*v3.w;
                }
            }
        }

        // ---- epilogue: normalized attention rows (q < len) ----
        #pragma unroll
        for (int i = 0; i < 4; i++) {
            int r = ty + 8 * i;
            if (q0 + r < len) {
                float inv = 1.0f / lrow[i];
                float4 o = make_float4(acc[i][0]*inv, acc[i][1]*inv,
                                       acc[i][2]*inv, acc[i][3]*inv);
                *(float4*)(ob + r * HD + 4 * tx) = o;
            }
        }
    }

    if (any_mean) {
        // Fully-masked rows: softmax over all-NEG scores is uniform ->
        // output = mean(v[b], axis=0). Compute cooperatively (v[b] is L2-resident).
        __syncthreads();
        const int c    = tid & (HD - 1);
        const int part = tid >> 7;          // 0 or 1
        float sum = 0.f;
        const float* vp = vb + (long)part * HD + c;
        #pragma unroll 8
        for (int s = 0; s < SEQ / 2; s++) sum += vp[(long)s * 2 * HD];
        sP[part * HD + c] = sum;
        __syncthreads();
        if (tid < HD) sQ[tid] = (sP[tid] + sP[HD + tid]) * (1.0f / SEQ);
        __syncthreads();
        int rstart = len - q0; if (rstart < 0) rstart = 0;
        for (int idx = tid; idx < (BM - rstart) * HD; idx += NTH) {
            int r  = rstart + (idx >> 7);
            int cc = idx & (HD - 1);
            ob[r * HD + cc] = sQ[cc];
        }
    }
}

extern "C" void kernel_launch(void* const* d_in, const int* in_sizes, int n_in,
                              void* d_out, int out_size)
{
    const float* q    = (const float*)d_in[0];
    const float* k    = (const float*)d_in[1];
    const float* v    = (const float*)d_in[2];
    const int*   lens = (const int*)d_in[3];
    float*       out  = (float*)d_out;

    const int smem_bytes = SMEM_FLOATS * (int)sizeof(float);   // 92,672 B
    cudaFuncSetAttribute(attn_kernel,
                         cudaFuncAttributeMaxDynamicSharedMemorySize, smem_bytes);

    dim3 grid(SEQ / BM, NB);   // 64 x 8 = 512 CTAs
    attn_kernel<<<grid, NTH, smem_bytes>>>(q, k, v, lens, out);
}

// round 9
// speedup vs baseline: 1.3044x; 1.3044x over previous
#include <cuda_runtime.h>
#include <cuda_bf16.h>
#include <stdint.h>
#include <math.h>

#define NB   8
#define SEQ  2048
#define HD   128
#define BM   64
#define BN   32
#define NTH  256
#define TSB  272      /* Q/K/V bf16 tile row stride BYTES (256 data + 16 pad) */
#define PSB  80       /* P bf16 row stride BYTES (64 data + 16 pad) */
#define SSTR 36       /* fp32 score row stride floats (32 + 4 pad) */
#define NEGV (-1.0e9f)

/* smem byte offsets */
#define OQH 0         /* 64 x 272 = 17408 */
#define OQL 17408
#define OKH 34816     /* 32 x 272 =  8704 */
#define OKL 43520
#define OVH 52224
#define OVL 60928
#define OS  69632     /* 64 x 36 x 4 = 9216 */
#define OPH 78848     /* 64 x 80 = 5120 */
#define OPL 83968
#define ORED 89088    /* alpha[64], linv[64] = 512 */
#define SMBYTES 89600

__device__ __forceinline__ uint32_t smaddr(const void* p) {
    return (uint32_t)__cvta_generic_to_shared(p);
}
__device__ __forceinline__ void ldsm4(uint32_t a, uint32_t& r0, uint32_t& r1,
                                      uint32_t& r2, uint32_t& r3) {
    asm volatile("ldmatrix.sync.aligned.m8n8.x4.shared.b16 {%0,%1,%2,%3}, [%4];"
                 : "=r"(r0), "=r"(r1), "=r"(r2), "=r"(r3) : "r"(a));
}
__device__ __forceinline__ void ldsm4t(uint32_t a, uint32_t& r0, uint32_t& r1,
                                       uint32_t& r2, uint32_t& r3) {
    asm volatile("ldmatrix.sync.aligned.m8n8.x4.trans.shared.b16 {%0,%1,%2,%3}, [%4];"
                 : "=r"(r0), "=r"(r1), "=r"(r2), "=r"(r3) : "r"(a));
}
__device__ __forceinline__ void mma16816(float* c, uint32_t a0, uint32_t a1, uint32_t a2,
                                         uint32_t a3, uint32_t b0, uint32_t b1) {
    asm volatile("mma.sync.aligned.m16n8k16.row.col.f32.bf16.bf16.f32 "
                 "{%0,%1,%2,%3}, {%4,%5,%6,%7}, {%8,%9}, {%0,%1,%2,%3};"
                 : "+f"(c[0]), "+f"(c[1]), "+f"(c[2]), "+f"(c[3])
                 : "r"(a0), "r"(a1), "r"(a2), "r"(a3), "r"(b0), "r"(b1));
}
/* split two fp32 -> packed hi/lo bf16 words (elem0 | elem1<<16, memory order) */
__device__ __forceinline__ void split2(float x0, float x1, uint32_t& h, uint32_t& l) {
    __nv_bfloat16 h0 = __float2bfloat16_rn(x0);
    __nv_bfloat16 h1 = __float2bfloat16_rn(x1);
    h = (uint32_t)__bfloat16_as_ushort(h0) | ((uint32_t)__bfloat16_as_ushort(h1) << 16);
    float r0 = x0 - __bfloat162float(h0);
    float r1 = x1 - __bfloat162float(h1);
    __nv_bfloat16 l0 = __float2bfloat16_rn(r0);
    __nv_bfloat16 l1 = __float2bfloat16_rn(r1);
    l = (uint32_t)__bfloat16_as_ushort(l0) | ((uint32_t)__bfloat16_as_ushort(l1) << 16);
}

__global__ __launch_bounds__(NTH, 2)
void attn_kernel(const float* __restrict__ Q, const float* __restrict__ K,
                 const float* __restrict__ V, const int* __restrict__ LENS,
                 float* __restrict__ OUT)
{
    extern __shared__ char smc[];
    const uint32_t smb = smaddr(smc);
    float* sS    = (float*)(smc + OS);
    float* sAl   = (float*)(smc + ORED);
    float* sLinv = sAl + 64;

    const int b   = blockIdx.y;
    const int q0  = blockIdx.x * BM;
    const int len = LENS[b];
    const int tid = threadIdx.x;
    const int wid = tid >> 5;
    const int lane = tid & 31;

    /* mma warp grid: 4 row-blocks (16 rows) x 2 col-halves */
    const int wr = wid >> 1;
    const int wc = wid & 1;               /* score cols wc*16.. ; O cols wc*64.. */
    const int r0 = wr * 16 + (lane >> 2);

    const float* qb = Q + ((long)b * SEQ + q0) * HD;
    const float* kb = K + (long)b * SEQ * HD;
    const float* vb = V + (long)b * SEQ * HD;
    float*       ob = OUT + ((long)b * SEQ + q0) * HD;

    const bool any_attn = (q0 < len);
    const bool any_mean = (q0 + BM > len);

    if (any_attn) {
        /* ---- stage Q once (pre-scaled), split hi/lo bf16 ---- */
        const float scale = 0.088388347648318447f;  /* 1/sqrt(128) */
        for (int idx = tid * 4; idx < BM * HD; idx += NTH * 4) {
            float4 t = *(const float4*)(qb + idx);
            int r = idx >> 7, c = idx & (HD - 1);
            uint32_t h0, l0, h1, l1;
            split2(t.x * scale, t.y * scale, h0, l0);
            split2(t.z * scale, t.w * scale, h1, l1);
            *(uint2*)(smc + OQH + r * TSB + c * 2) = make_uint2(h0, h1);
            *(uint2*)(smc + OQL + r * TSB + c * 2) = make_uint2(l0, l1);
        }

        /* ldmatrix per-lane bases (all reads stay inside the 256B/64B data span) */
        const uint32_t qbase = smb + OQH + (wr * 16 + (lane & 15)) * TSB + ((lane >> 4) << 4);
        const uint32_t kbase = smb + OKH + (wc * 16 + (lane & 7) + ((lane >> 4) << 3)) * TSB
                                   + (((lane >> 3) & 1) << 4);
        const uint32_t pbase = smb + OPH + (wr * 16 + (lane & 15)) * PSB + ((lane >> 4) << 4);
        const uint32_t vbase = smb + OVH + (lane & 15) * TSB + ((lane >> 4) << 4) + wc * 128;

        float of[8][4];                    /* O: 8 n8-tiles over cols wc*64..+63 */
        #pragma unroll
        for (int i = 0; i < 8; i++)
            of[i][0] = of[i][1] = of[i][2] = of[i][3] = 0.f;
        float mrow[8], lrow[8];
        #pragma unroll
        for (int i = 0; i < 8; i++) { mrow[i] = -INFINITY; lrow[i] = 0.f; }

        const int nkt = (len + BN - 1) / BN;
        for (int kt = 0; kt < nkt; kt++) {
            __syncthreads();               /* prior PV done before K/V overwrite */
            /* ---- stage K,V tile (32 x 128), split hi/lo ---- */
            const float* kbt = kb + (long)kt * BN * HD;
            const float* vbt = vb + (long)kt * BN * HD;
            for (int idx = tid * 4; idx < BN * HD; idx += NTH * 4) {
                int r = idx >> 7, c = idx & (HD - 1);
                float4 t = *(const float4*)(kbt + idx);
                uint32_t h0, l0, h1, l1;
                split2(t.x, t.y, h0, l0);
                split2(t.z, t.w, h1, l1);
                *(uint2*)(smc + OKH + r * TSB + c * 2) = make_uint2(h0, h1);
                *(uint2*)(smc + OKL + r * TSB + c * 2) = make_uint2(l0, l1);
                t = *(const float4*)(vbt + idx);
                split2(t.x, t.y, h0, l0);
                split2(t.z, t.w, h1, l1);
                *(uint2*)(smc + OVH + r * TSB + c * 2) = make_uint2(h0, h1);
                *(uint2*)(smc + OVL + r * TSB + c * 2) = make_uint2(l0, l1);
            }
            __syncthreads();

            /* ---- scores: S(16x16 per warp) = Qs . K^T, 3-term split ---- */
            float sf[2][4];
            sf[0][0]=sf[0][1]=sf[0][2]=sf[0][3]=0.f;
            sf[1][0]=sf[1][1]=sf[1][2]=sf[1][3]=0.f;
            #pragma unroll
            for (int ks = 0; ks < 8; ks++) {
                uint32_t qh0,qh1,qh2,qh3, ql0,ql1,ql2,ql3;
                ldsm4(qbase + ks * 32,           qh0, qh1, qh2, qh3);
                ldsm4(qbase + (OQL-OQH) + ks*32, ql0, ql1, ql2, ql3);
                uint32_t bh0,bh1,bh2,bh3, bl0,bl1,bl2,bl3;
                ldsm4(kbase + ks * 32,           bh0, bh1, bh2, bh3);
                ldsm4(kbase + (OKL-OKH) + ks*32, bl0, bl1, bl2, bl3);
                mma16816(sf[0], qh0,qh1,qh2,qh3, bh0,bh1);
                mma16816(sf[0], qh0,qh1,qh2,qh3, bl0,bl1);
                mma16816(sf[0], ql0,ql1,ql2,ql3, bh0,bh1);
                mma16816(sf[1], qh0,qh1,qh2,qh3, bh2,bh3);
                mma16816(sf[1], qh0,qh1,qh2,qh3, bl2,bl3);
                mma16816(sf[1], ql0,ql1,ql2,ql3, bh2,bh3);
            }
            {   /* store score frags */
                float* srow = sS + r0 * SSTR + wc * 16 + 2 * (lane & 3);
                *(float2*)(srow + 0)            = make_float2(sf[0][0], sf[0][1]);
                *(float2*)(srow + 8)            = make_float2(sf[1][0], sf[1][1]);
                *(float2*)(srow + 8 * SSTR)     = make_float2(sf[0][2], sf[0][3]);
                *(float2*)(srow + 8 * SSTR + 8) = make_float2(sf[1][2], sf[1][3]);
            }
            __syncthreads();

            /* ---- online softmax: warp wid owns rows wid+8i; lane owns col `lane` ---- */
            const int kc = kt * BN + lane;
            #pragma unroll
            for (int i = 0; i < 8; i++) {
                int row = wid + 8 * i;
                float s = sS[row * SSTR + lane];
                if (kc >= len) s = NEGV;
                float tm = s;
                #pragma unroll
                for (int off = 16; off > 0; off >>= 1)
                    tm = fmaxf(tm, __shfl_xor_sync(0xffffffffu, tm, off));
                float mnew  = fmaxf(mrow[i], tm);
                float alpha = __expf(mrow[i] - mnew);   /* exp(-inf)=0 first tile */
                mrow[i] = mnew;
                float p = __expf(s - mnew);             /* masked -> 0 */
                float rs = p;
                #pragma unroll
                for (int off = 16; off > 0; off >>= 1)
                    rs += __shfl_xor_sync(0xffffffffu, rs, off);
                lrow[i] = lrow[i] * alpha + rs;
                __nv_bfloat16 ph = __float2bfloat16_rn(p);
                __nv_bfloat16 pl = __float2bfloat16_rn(p - __bfloat162float(ph));
                *(unsigned short*)(smc + OPH + row * PSB + 2 * lane) = __bfloat16_as_ushort(ph);
                *(unsigned short*)(smc + OPL + row * PSB + 2 * lane) = __bfloat16_as_ushort(pl);
                if (lane == 0) sAl[row] = alpha;
            }
            __syncthreads();

            /* ---- rescale O, then O += P @ V (3-term split) ---- */
            {
                float a0 = sAl[r0], a1 = sAl[r0 + 8];
                #pragma unroll
                for (int nt = 0; nt < 8; nt++) {
                    of[nt][0] *= a0; of[nt][1] *= a0;
                    of[nt][2] *= a1; of[nt][3] *= a1;
                }
            }
            #pragma unroll
            for (int ks = 0; ks < 2; ks++) {
                uint32_t ph0,ph1,ph2,ph3, pl0,pl1,pl2,pl3;
                ldsm4(pbase + ks * 32,           ph0, ph1, ph2, ph3);
                ldsm4(pbase + (OPL-OPH) + ks*32, pl0, pl1, pl2, pl3);
                #pragma unroll
                for (int ntp = 0; ntp < 4; ntp++) {
                    uint32_t vh0,vh1,vh2,vh3, vl0,vl1,vl2,vl3;
                    uint32_t va = vbase + ks * (16 * TSB) + ntp * 32;
                    ldsm4t(va,             vh0, vh1, vh2, vh3);
                    ldsm4t(va + (OVL-OVH), vl0, vl1, vl2, vl3);
                    mma16816(of[ntp*2],   ph0,ph1,ph2,ph3, vh0,vh1);
                    mma16816(of[ntp*2],   ph0,ph1,ph2,ph3, vl0,vl1);
                    mma16816(of[ntp*2],   pl0,pl1,pl2,pl3, vh0,vh1);
                    mma16816(of[ntp*2+1], ph0,ph1,ph2,ph3, vh2,vh3);
                    mma16816(of[ntp*2+1], ph0,ph1,ph2,ph3, vl2,vl3);
                    mma16816(of[ntp*2+1], pl0,pl1,pl2,pl3, vh2,vh3);
                }
            }
        }

        /* ---- epilogue ---- */
        #pragma unroll
        for (int i = 0; i < 8; i++)
            if (lane == 0) sLinv[wid + 8 * i] = 1.0f / lrow[i];
        __syncthreads();
        {
            float i0 = sLinv[r0], i1 = sLinv[r0 + 8];
            bool w0 = (q0 + r0 < len), w1 = (q0 + r0 + 8 < len);
            float* o0 = ob + r0 * HD + wc * 64 + 2 * (lane & 3);
            #pragma unroll
            for (int nt = 0; nt < 8; nt++) {
                if (w0) *(float2*)(o0 + nt * 8)          = make_float2(of[nt][0]*i0, of[nt][1]*i0);
                if (w1) *(float2*)(o0 + 8 * HD + nt * 8) = make_float2(of[nt][2]*i1, of[nt][3]*i1);
            }
        }
    }

    if (any_mean) {
        /* fully-masked rows -> uniform softmax -> mean(v[b], axis=0) */
        __syncthreads();
        float* scr = sS;
        const int c    = tid & (HD - 1);
        const int part = tid >> 7;
        float sum = 0.f;
        const float* vp = vb + (long)part * HD + c;
        #pragma unroll 8
        for (int s = 0; s < SEQ / 2; s++) sum += vp[(long)s * 2 * HD];
        scr[part * HD + c] = sum;
        __syncthreads();
        if (tid < HD) scr[2 * HD + tid] = (scr[tid] + scr[HD + tid]) * (1.0f / SEQ);
        __syncthreads();
        int rstart = len - q0; if (rstart < 0) rstart = 0;
        for (int idx = tid; idx < (BM - rstart) * HD; idx += NTH) {
            int r  = rstart + (idx >> 7);
            int cc = idx & (HD - 1);
            ob[r * HD + cc] = scr[2 * HD + cc];
        }
    }
}

extern "C" void kernel_launch(void* const* d_in, const int* in_sizes, int n_in,
                              void* d_out, int out_size)
{
    const float* q    = (const float*)d_in[0];
    const float* k    = (const float*)d_in[1];
    const float* v    = (const float*)d_in[2];
    const int*   lens = (const int*)d_in[3];
    float*       out  = (float*)d_out;

    cudaFuncSetAttribute(attn_kernel,
                         cudaFuncAttributeMaxDynamicSharedMemorySize, SMBYTES);

    dim3 grid(SEQ / BM, NB);   /* 32 x 8 = 256 CTAs, single wave at 2 CTA/SM */
    attn_kernel<<<grid, NTH, SMBYTES>>>(q, k, v, lens, out);
}

// round 11
// speedup vs baseline: 1.9872x; 1.5235x over previous
#include <cuda_runtime.h>
#include <cuda_bf16.h>
#include <stdint.h>
#include <math.h>

#define NB   8
#define SEQ  2048
#define HD   128
#define BM   64
#define BN   32
#define NTH  256
#define TSB  272      /* Q/K/V bf16 row stride BYTES (256 data + 16 pad) */
#define PSB  80       /* P bf16 row stride BYTES (64 data + 16 pad) */
#define NEGV (-1.0e9f)

/* smem byte offsets */
#define OQH 0         /* 64 x 272 = 17408 */
#define OQL 17408
#define OKH 34816     /* 32 x 272 = 8704 */
#define OKL 43520
#define OVH 52224
#define OVL 60928
#define OPH 69632     /* 64 x 80 = 5120 */
#define OPL 74752
#define ORED 79872    /* 128-float exchange (m / l halves) */
#define SMBYTES 80384

__device__ __forceinline__ uint32_t smaddr(const void* p) {
    return (uint32_t)__cvta_generic_to_shared(p);
}
__device__ __forceinline__ void ldsm4(uint32_t a, uint32_t& r0, uint32_t& r1,
                                      uint32_t& r2, uint32_t& r3) {
    asm volatile("ldmatrix.sync.aligned.m8n8.x4.shared.b16 {%0,%1,%2,%3}, [%4];"
                 : "=r"(r0), "=r"(r1), "=r"(r2), "=r"(r3) : "r"(a));
}
__device__ __forceinline__ void ldsm4t(uint32_t a, uint32_t& r0, uint32_t& r1,
                                       uint32_t& r2, uint32_t& r3) {
    asm volatile("ldmatrix.sync.aligned.m8n8.x4.trans.shared.b16 {%0,%1,%2,%3}, [%4];"
                 : "=r"(r0), "=r"(r1), "=r"(r2), "=r"(r3) : "r"(a));
}
__device__ __forceinline__ void mma16816(float* c, uint32_t a0, uint32_t a1, uint32_t a2,
                                         uint32_t a3, uint32_t b0, uint32_t b1) {
    asm volatile("mma.sync.aligned.m16n8k16.row.col.f32.bf16.bf16.f32 "
                 "{%0,%1,%2,%3}, {%4,%5,%6,%7}, {%8,%9}, {%0,%1,%2,%3};"
                 : "+f"(c[0]), "+f"(c[1]), "+f"(c[2]), "+f"(c[3])
                 : "r"(a0), "r"(a1), "r"(a2), "r"(a3), "r"(b0), "r"(b1));
}
/* split two fp32 -> packed hi/lo bf16 words (elem0 | elem1<<16, memory order) */
__device__ __forceinline__ void split2(float x0, float x1, uint32_t& h, uint32_t& l) {
    __nv_bfloat16 h0 = __float2bfloat16_rn(x0);
    __nv_bfloat16 h1 = __float2bfloat16_rn(x1);
    h = (uint32_t)__bfloat16_as_ushort(h0) | ((uint32_t)__bfloat16_as_ushort(h1) << 16);
    float r0 = x0 - __bfloat162float(h0);
    float r1 = x1 - __bfloat162float(h1);
    __nv_bfloat16 l0 = __float2bfloat16_rn(r0);
    __nv_bfloat16 l1 = __float2bfloat16_rn(r1);
    l = (uint32_t)__bfloat16_as_ushort(l0) | ((uint32_t)__bfloat16_as_ushort(l1) << 16);
}

__global__ __launch_bounds__(NTH, 2)
void attn_kernel(const float* __restrict__ Q, const float* __restrict__ K,
                 const float* __restrict__ V, const int* __restrict__ LENS,
                 float* __restrict__ OUT)
{
    extern __shared__ char smc[];
    const uint32_t smb = smaddr(smc);
    float* sM = (float*)(smc + ORED);   /* 128 floats: [half][row] */

    const int b    = blockIdx.y;
    const int q0   = blockIdx.x * BM;
    const int len  = LENS[b];
    const int tid  = threadIdx.x;
    const int wid  = tid >> 5;
    const int lane = tid & 31;

    const int wr = wid & 3;            /* row block: rows 16wr..16wr+15 */
    const int wh = wid >> 2;           /* half: score cols wh*16.. , O cols wh*64.. */
    const int rq = lane >> 2;          /* 0..7 */
    const int row0 = wr * 16 + rq;     /* + 8 for second row */

    const float* qb = Q + ((long)b * SEQ + q0) * HD;
    const float* kb = K + (long)b * SEQ * HD;
    const float* vb = V + (long)b * SEQ * HD;
    float*       ob = OUT + ((long)b * SEQ + q0) * HD;

    const bool any_attn = (q0 < len);
    const bool any_mean = (q0 + BM > len);

    if (any_attn) {
        /* ---- stage Q once (pre-scaled), split hi/lo bf16 ---- */
        const float scale = 0.088388347648318447f;  /* 1/sqrt(128) */
        for (int idx = tid * 4; idx < BM * HD; idx += NTH * 4) {
            float4 t = *(const float4*)(qb + idx);
            int r = idx >> 7, c = idx & (HD - 1);
            uint32_t h0, l0, h1, l1;
            split2(t.x * scale, t.y * scale, h0, l0);
            split2(t.z * scale, t.w * scale, h1, l1);
            *(uint2*)(smc + OQH + r * TSB + c * 2) = make_uint2(h0, h1);
            *(uint2*)(smc + OQL + r * TSB + c * 2) = make_uint2(l0, l1);
        }
        /* ---- stage K/V tile 0 directly ---- */
        for (int idx = tid * 4; idx < BN * HD; idx += NTH * 4) {
            int r = idx >> 7, c = idx & (HD - 1);
            float4 t = *(const float4*)(kb + idx);
            uint32_t h0, l0, h1, l1;
            split2(t.x, t.y, h0, l0); split2(t.z, t.w, h1, l1);
            *(uint2*)(smc + OKH + r * TSB + c * 2) = make_uint2(h0, h1);
            *(uint2*)(smc + OKL + r * TSB + c * 2) = make_uint2(l0, l1);
            t = *(const float4*)(vb + idx);
            split2(t.x, t.y, h0, l0); split2(t.z, t.w, h1, l1);
            *(uint2*)(smc + OVH + r * TSB + c * 2) = make_uint2(h0, h1);
            *(uint2*)(smc + OVL + r * TSB + c * 2) = make_uint2(l0, l1);
        }

        const uint32_t qbase = smb + OQH + (wr * 16 + (lane & 15)) * TSB + ((lane >> 4) << 4);
        const uint32_t kbase = smb + OKH + (wh * 16 + (lane & 7) + ((lane >> 4) << 3)) * TSB
                                   + (((lane >> 3) & 1) << 4);
        const uint32_t pbase = smb + OPH + (wr * 16 + (lane & 15)) * PSB + ((lane >> 4) << 4);
        const uint32_t vbase = smb + OVH + (lane & 15) * TSB + ((lane >> 4) << 4) + wh * 128;

        float of[8][4];               /* O: 16 rows x 64 HD cols (wh half) */
        #pragma unroll
        for (int i = 0; i < 8; i++)
            of[i][0] = of[i][1] = of[i][2] = of[i][3] = 0.f;
        float m0r = -INFINITY, m1r = -INFINITY, l0r = 0.f, l1r = 0.f;

        __syncthreads();

        const int nkt = (len + BN - 1) / BN;
        for (int kt = 0; kt < nkt; kt++) {
            /* prefetch next K/V tile into registers (latency hidden behind MMAs) */
            float4 kreg[4], vreg[4];
            const bool pf = (kt + 1 < nkt);
            if (pf) {
                const float* kbt = kb + (long)(kt + 1) * BN * HD;
                const float* vbt = vb + (long)(kt + 1) * BN * HD;
                #pragma unroll
                for (int j = 0; j < 4; j++) {
                    int idx = tid * 4 + j * (NTH * 4);
                    kreg[j] = *(const float4*)(kbt + idx);
                    vreg[j] = *(const float4*)(vbt + idx);
                }
            }

            /* ---- scores: 16x16 per warp, 3-term split-bf16, stay in regs ---- */
            float sf0[4] = {0.f,0.f,0.f,0.f};   /* key cols wh*16 + 0..7  */
            float sf1[4] = {0.f,0.f,0.f,0.f};   /* key cols wh*16 + 8..15 */
            #pragma unroll
            for (int ks = 0; ks < 8; ks++) {
                uint32_t qh0,qh1,qh2,qh3, ql0,ql1,ql2,ql3;
                ldsm4(qbase + ks * 32,             qh0, qh1, qh2, qh3);
                ldsm4(qbase + (OQL-OQH) + ks * 32, ql0, ql1, ql2, ql3);
                uint32_t bh0,bh1,bh2,bh3, bl0,bl1,bl2,bl3;
                ldsm4(kbase + ks * 32,             bh0, bh1, bh2, bh3);
                ldsm4(kbase + (OKL-OKH) + ks * 32, bl0, bl1, bl2, bl3);
                mma16816(sf0, qh0,qh1,qh2,qh3, bh0,bh1);
                mma16816(sf0, qh0,qh1,qh2,qh3, bl0,bl1);
                mma16816(sf0, ql0,ql1,ql2,ql3, bh0,bh1);
                mma16816(sf1, qh0,qh1,qh2,qh3, bh2,bh3);
                mma16816(sf1, qh0,qh1,qh2,qh3, bl2,bl3);
                mma16816(sf1, ql0,ql1,ql2,ql3, bh2,bh3);
            }

            /* mask (only last tile can be partial) */
            if (kt == nkt - 1) {
                int c0 = kt * BN + wh * 16 + 2 * (lane & 3);
                if (c0     >= len) { sf0[0] = NEGV; sf0[2] = NEGV; }
                if (c0 + 1 >= len) { sf0[1] = NEGV; sf0[3] = NEGV; }
                if (c0 + 8 >= len) { sf1[0] = NEGV; sf1[2] = NEGV; }
                if (c0 + 9 >= len) { sf1[1] = NEGV; sf1[3] = NEGV; }
            }

            /* partial row max over this warp's 16 cols: quad shfl (2 steps) */
            float pm0 = fmaxf(fmaxf(sf0[0], sf0[1]), fmaxf(sf1[0], sf1[1]));
            float pm1 = fmaxf(fmaxf(sf0[2], sf0[3]), fmaxf(sf1[2], sf1[3]));
            pm0 = fmaxf(pm0, __shfl_xor_sync(0xffffffffu, pm0, 1));
            pm0 = fmaxf(pm0, __shfl_xor_sync(0xffffffffu, pm0, 2));
            pm1 = fmaxf(pm1, __shfl_xor_sync(0xffffffffu, pm1, 1));
            pm1 = fmaxf(pm1, __shfl_xor_sync(0xffffffffu, pm1, 2));
            if ((lane & 3) == 0) {
                sM[wh * 64 + row0]     = pm0;
                sM[wh * 64 + row0 + 8] = pm1;
            }
            __syncthreads();   /* S1: scores done (sK free), m exchanged */

            /* store prefetched K for next tile (sK free now) */
            if (pf) {
                #pragma unroll
                for (int j = 0; j < 4; j++) {
                    int idx = tid * 4 + j * (NTH * 4);
                    int r = idx >> 7, c = idx & (HD - 1);
                    uint32_t h0, l0, h1, l1;
                    split2(kreg[j].x, kreg[j].y, h0, l0);
                    split2(kreg[j].z, kreg[j].w, h1, l1);
                    *(uint2*)(smc + OKH + r * TSB + c * 2) = make_uint2(h0, h1);
                    *(uint2*)(smc + OKL + r * TSB + c * 2) = make_uint2(l0, l1);
                }
            }

            /* joint max (pair exchange), softmax in registers */
            float om0 = sM[(wh ^ 1) * 64 + row0];
            float om1 = sM[(wh ^ 1) * 64 + row0 + 8];
            float mn0 = fmaxf(m0r, fmaxf(pm0, om0));
            float mn1 = fmaxf(m1r, fmaxf(pm1, om1));
            float a0 = __expf(m0r - mn0);   /* exp(-inf)=0 on first tile */
            float a1 = __expf(m1r - mn1);
            m0r = mn0; m1r = mn1;
            float p00 = __expf(sf0[0] - mn0), p01 = __expf(sf0[1] - mn0);
            float p08 = __expf(sf1[0] - mn0), p09 = __expf(sf1[1] - mn0);
            float p10 = __expf(sf0[2] - mn1), p11 = __expf(sf0[3] - mn1);
            float p18 = __expf(sf1[2] - mn1), p19 = __expf(sf1[3] - mn1);
            float ls0 = p00 + p01 + p08 + p09;
            float ls1 = p10 + p11 + p18 + p19;
            ls0 += __shfl_xor_sync(0xffffffffu, ls0, 1);
            ls0 += __shfl_xor_sync(0xffffffffu, ls0, 2);
            ls1 += __shfl_xor_sync(0xffffffffu, ls1, 1);
            ls1 += __shfl_xor_sync(0xffffffffu, ls1, 2);
            l0r = l0r * a0 + ls0;          /* per-half l; merged at epilogue */
            l1r = l1r * a1 + ls1;

            /* pack P hi/lo (C-frag == A-frag layout) and store this warp's 16-col half */
            {
                uint32_t h, l;
                char* pr0 = smc + OPH + row0 * PSB + (wh * 16 + 2 * (lane & 3)) * 2;
                char* pr1 = pr0 + 8 * PSB;
                split2(p00, p01, h, l);
                *(uint32_t*)(pr0)                    = h;
                *(uint32_t*)(pr0 + (OPL - OPH))      = l;
                split2(p08, p09, h, l);
                *(uint32_t*)(pr0 + 16)               = h;
                *(uint32_t*)(pr0 + 16 + (OPL - OPH)) = l;
                split2(p10, p11, h, l);
                *(uint32_t*)(pr1)                    = h;
                *(uint32_t*)(pr1 + (OPL - OPH))      = l;
                split2(p18, p19, h, l);
                *(uint32_t*)(pr1 + 16)               = h;
                *(uint32_t*)(pr1 + 16 + (OPL - OPH)) = l;
            }

            /* rescale O by alpha */
            #pragma unroll
            for (int nt = 0; nt < 8; nt++) {
                of[nt][0] *= a0; of[nt][1] *= a0;
                of[nt][2] *= a1; of[nt][3] *= a1;
            }
            __syncthreads();   /* S2: full-width P ready */

            /* ---- O += P(16x32 full) @ V(32 x 64-col half), 3-term ---- */
            #pragma unroll
            for (int ks = 0; ks < 2; ks++) {
                uint32_t ph0,ph1,ph2,ph3, pl0,pl1,pl2,pl3;
                ldsm4(pbase + ks * 32,             ph0, ph1, ph2, ph3);
                ldsm4(pbase + (OPL-OPH) + ks * 32, pl0, pl1, pl2, pl3);
                #pragma unroll
                for (int ntp = 0; ntp < 4; ntp++) {
                    uint32_t vh0,vh1,vh2,vh3, vl0,vl1,vl2,vl3;
                    uint32_t va = vbase + ks * (16 * TSB) + ntp * 32;
                    ldsm4t(va,              vh0, vh1, vh2, vh3);
                    ldsm4t(va + (OVL-OVH),  vl0, vl1, vl2, vl3);
                    mma16816(of[ntp*2],   ph0,ph1,ph2,ph3, vh0,vh1);
                    mma16816(of[ntp*2],   ph0,ph1,ph2,ph3, vl0,vl1);
                    mma16816(of[ntp*2],   pl0,pl1,pl2,pl3, vh0,vh1);
                    mma16816(of[ntp*2+1], ph0,ph1,ph2,ph3, vh2,vh3);
                    mma16816(of[ntp*2+1], ph0,ph1,ph2,ph3, vl2,vl3);
                    mma16816(of[ntp*2+1], pl0,pl1,pl2,pl3, vh2,vh3);
                }
            }
            __syncthreads();   /* S3: PV reads done -> sV free */

            /* store prefetched V for next tile */
            if (pf) {
                #pragma unroll
                for (int j = 0; j < 4; j++) {
                    int idx = tid * 4 + j * (NTH * 4);
                    int r = idx >> 7, c = idx & (HD - 1);
                    uint32_t h0, l0, h1, l1;
                    split2(vreg[j].x, vreg[j].y, h0, l0);
                    split2(vreg[j].z, vreg[j].w, h1, l1);
                    *(uint2*)(smc + OVH + r * TSB + c * 2) = make_uint2(h0, h1);
                    *(uint2*)(smc + OVL + r * TSB + c * 2) = make_uint2(l0, l1);
                }
            }
        }

        /* ---- epilogue: merge l halves, normalize, store rows < len ---- */
        if ((lane & 3) == 0) {
            sM[wh * 64 + row0]     = l0r;
            sM[wh * 64 + row0 + 8] = l1r;
        }
        __syncthreads();
        {
            float lj0 = l0r + sM[(wh ^ 1) * 64 + row0];
            float lj1 = l1r + sM[(wh ^ 1) * 64 + row0 + 8];
            float i0 = 1.0f / lj0, i1 = 1.0f / lj1;
            bool w0 = (q0 + row0 < len), w1 = (q0 + row0 + 8 < len);
            float* o0 = ob + row0 * HD + wh * 64 + 2 * (lane & 3);
            #pragma unroll
            for (int nt = 0; nt < 8; nt++) {
                if (w0) *(float2*)(o0 + nt * 8)          = make_float2(of[nt][0]*i0, of[nt][1]*i0);
                if (w1) *(float2*)(o0 + 8 * HD + nt * 8) = make_float2(of[nt][2]*i1, of[nt][3]*i1);
            }
        }
    }

    if (any_mean) {
        /* fully-masked rows -> uniform softmax -> mean(v[b], axis=0) */
        __syncthreads();
        float* scr = (float*)(smc + OPH);
        const int c    = tid & (HD - 1);
        const int part = tid >> 7;
        float sum = 0.f;
        const float* vp = vb + (long)part * HD + c;
        #pragma unroll 8
        for (int s = 0; s < SEQ / 2; s++) sum += vp[(long)s * 2 * HD];
        scr[part * HD + c] = sum;
        __syncthreads();
        if (tid < HD) scr[2 * HD + tid] = (scr[tid] + scr[HD + tid]) * (1.0f / SEQ);
        __syncthreads();
        int rstart = len - q0; if (rstart < 0) rstart = 0;
        for (int idx = tid; idx < (BM - rstart) * HD; idx += NTH) {
            int r  = rstart + (idx >> 7);
            int cc = idx & (HD - 1);
            ob[r * HD + cc] = scr[2 * HD + cc];
        }
    }
}

extern "C" void kernel_launch(void* const* d_in, const int* in_sizes, int n_in,
                              void* d_out, int out_size)
{
    const float* q    = (const float*)d_in[0];
    const float* k    = (const float*)d_in[1];
    const float* v    = (const float*)d_in[2];
    const int*   lens = (const int*)d_in[3];
    float*       out  = (float*)d_out;

    cudaFuncSetAttribute(attn_kernel,
                         cudaFuncAttributeMaxDynamicSharedMemorySize, SMBYTES);

    dim3 grid(SEQ / BM, NB);   /* 32 x 8 = 256 CTAs, single wave at 2 CTA/SM */
    attn_kernel<<<grid, NTH, SMBYTES>>>(q, k, v, lens, out);
}

// round 12
// speedup vs baseline: 2.6295x; 1.3232x over previous
#include <cuda_runtime.h>
#include <cuda_bf16.h>
#include <stdint.h>
#include <math.h>

#define NB   8
#define SEQ  2048
#define HD   128
#define BM   64
#define BN   32
#define NCH  4        /* key chunks of 512 */
#define CHK  512
#define NTH  256
#define TSB  272      /* Q/K/V bf16 row stride BYTES (256 data + 16 pad) */
#define PSB  80       /* P bf16 row stride BYTES (64 data + 16 pad) */
#define NEGV (-1.0e9f)

/* smem byte offsets */
#define OQH 0
#define OQL 17408
#define OKH 34816
#define OKL 43520
#define OVH 52224
#define OVL 60928
#define OPH 69632
#define OPL 74752
#define ORED 79872
#define SMBYTES 80384

/* split-K scratch: zero-initialized device globals (never-written slots stay 0) */
__device__ float g_po[(long)NB * 32 * NCH * BM * HD];  /* unnormalized O partials */
__device__ float g_pm[NB * 32 * NCH * BM];             /* row max  */
__device__ float g_pl[NB * 32 * NCH * BM];             /* row sum  */

__device__ __forceinline__ uint32_t smaddr(const void* p) {
    return (uint32_t)__cvta_generic_to_shared(p);
}
__device__ __forceinline__ void ldsm4(uint32_t a, uint32_t& r0, uint32_t& r1,
                                      uint32_t& r2, uint32_t& r3) {
    asm volatile("ldmatrix.sync.aligned.m8n8.x4.shared.b16 {%0,%1,%2,%3}, [%4];"
                 : "=r"(r0), "=r"(r1), "=r"(r2), "=r"(r3) : "r"(a));
}
__device__ __forceinline__ void ldsm4t(uint32_t a, uint32_t& r0, uint32_t& r1,
                                       uint32_t& r2, uint32_t& r3) {
    asm volatile("ldmatrix.sync.aligned.m8n8.x4.trans.shared.b16 {%0,%1,%2,%3}, [%4];"
                 : "=r"(r0), "=r"(r1), "=r"(r2), "=r"(r3) : "r"(a));
}
__device__ __forceinline__ void mma16816(float* c, uint32_t a0, uint32_t a1, uint32_t a2,
                                         uint32_t a3, uint32_t b0, uint32_t b1) {
    asm volatile("mma.sync.aligned.m16n8k16.row.col.f32.bf16.bf16.f32 "
                 "{%0,%1,%2,%3}, {%4,%5,%6,%7}, {%8,%9}, {%0,%1,%2,%3};"
                 : "+f"(c[0]), "+f"(c[1]), "+f"(c[2]), "+f"(c[3])
                 : "r"(a0), "r"(a1), "r"(a2), "r"(a3), "r"(b0), "r"(b1));
}
__device__ __forceinline__ void split2(float x0, float x1, uint32_t& h, uint32_t& l) {
    __nv_bfloat16 h0 = __float2bfloat16_rn(x0);
    __nv_bfloat16 h1 = __float2bfloat16_rn(x1);
    h = (uint32_t)__bfloat16_as_ushort(h0) | ((uint32_t)__bfloat16_as_ushort(h1) << 16);
    float r0 = x0 - __bfloat162float(h0);
    float r1 = x1 - __bfloat162float(h1);
    __nv_bfloat16 l0 = __float2bfloat16_rn(r0);
    __nv_bfloat16 l1 = __float2bfloat16_rn(r1);
    l = (uint32_t)__bfloat16_as_ushort(l0) | ((uint32_t)__bfloat16_as_ushort(l1) << 16);
}

/* ---------------- kernel 1: per-chunk flash partials ---------------- */
__global__ __launch_bounds__(NTH, 2)
void attn_part_kernel(const float* __restrict__ Q, const float* __restrict__ K,
                      const float* __restrict__ V, const int* __restrict__ LENS)
{
    extern __shared__ char smc[];
    const uint32_t smb = smaddr(smc);
    float* sM = (float*)(smc + ORED);

    const int b    = blockIdx.y;
    const int qb   = blockIdx.x;
    const int q0   = qb * BM;
    const int ch   = blockIdx.z;
    const int len  = LENS[b];
    const int kstart = ch * CHK;
    if (q0 >= len || kstart >= len) return;
    const int kend = (len < kstart + CHK) ? len : (kstart + CHK);

    const int tid  = threadIdx.x;
    const int wid  = tid >> 5;
    const int lane = tid & 31;
    const int wr = wid & 3;
    const int wh = wid >> 2;
    const int rq = lane >> 2;
    const int row0 = wr * 16 + rq;

    const float* qbp = Q + ((long)b * SEQ + q0) * HD;
    const float* kb  = K + (long)b * SEQ * HD;
    const float* vb  = V + (long)b * SEQ * HD;

    /* ---- stage Q (pre-scaled), split hi/lo ---- */
    const float scale = 0.088388347648318447f;
    for (int idx = tid * 4; idx < BM * HD; idx += NTH * 4) {
        float4 t = *(const float4*)(qbp + idx);
        int r = idx >> 7, c = idx & (HD - 1);
        uint32_t h0, l0, h1, l1;
        split2(t.x * scale, t.y * scale, h0, l0);
        split2(t.z * scale, t.w * scale, h1, l1);
        *(uint2*)(smc + OQH + r * TSB + c * 2) = make_uint2(h0, h1);
        *(uint2*)(smc + OQL + r * TSB + c * 2) = make_uint2(l0, l1);
    }
    /* ---- stage first K/V tile of this chunk ---- */
    {
        const float* kbt = kb + (long)kstart * HD;
        const float* vbt = vb + (long)kstart * HD;
        for (int idx = tid * 4; idx < BN * HD; idx += NTH * 4) {
            int r = idx >> 7, c = idx & (HD - 1);
            float4 t = *(const float4*)(kbt + idx);
            uint32_t h0, l0, h1, l1;
            split2(t.x, t.y, h0, l0); split2(t.z, t.w, h1, l1);
            *(uint2*)(smc + OKH + r * TSB + c * 2) = make_uint2(h0, h1);
            *(uint2*)(smc + OKL + r * TSB + c * 2) = make_uint2(l0, l1);
            t = *(const float4*)(vbt + idx);
            split2(t.x, t.y, h0, l0); split2(t.z, t.w, h1, l1);
            *(uint2*)(smc + OVH + r * TSB + c * 2) = make_uint2(h0, h1);
            *(uint2*)(smc + OVL + r * TSB + c * 2) = make_uint2(l0, l1);
        }
    }

    const uint32_t qbase = smb + OQH + (wr * 16 + (lane & 15)) * TSB + ((lane >> 4) << 4);
    const uint32_t kbase = smb + OKH + (wh * 16 + (lane & 7) + ((lane >> 4) << 3)) * TSB
                               + (((lane >> 3) & 1) << 4);
    const uint32_t pbase = smb + OPH + (wr * 16 + (lane & 15)) * PSB + ((lane >> 4) << 4);
    const uint32_t vbase = smb + OVH + (lane & 15) * TSB + ((lane >> 4) << 4) + wh * 128;

    float of[8][4];
    #pragma unroll
    for (int i = 0; i < 8; i++)
        of[i][0] = of[i][1] = of[i][2] = of[i][3] = 0.f;
    float m0r = -INFINITY, m1r = -INFINITY, l0r = 0.f, l1r = 0.f;

    __syncthreads();

    const int nloc = (kend - kstart + BN - 1) / BN;
    for (int lt = 0; lt < nloc; lt++) {
        float4 kreg[4], vreg[4];
        const bool pf = (lt + 1 < nloc);
        if (pf) {
            const float* kbt = kb + (long)(kstart + (lt + 1) * BN) * HD;
            const float* vbt = vb + (long)(kstart + (lt + 1) * BN) * HD;
            #pragma unroll
            for (int j = 0; j < 4; j++) {
                int idx = tid * 4 + j * (NTH * 4);
                kreg[j] = *(const float4*)(kbt + idx);
                vreg[j] = *(const float4*)(vbt + idx);
            }
        }

        float sf0[4] = {0.f,0.f,0.f,0.f};
        float sf1[4] = {0.f,0.f,0.f,0.f};
        #pragma unroll
        for (int ks = 0; ks < 8; ks++) {
            uint32_t qh0,qh1,qh2,qh3, ql0,ql1,ql2,ql3;
            ldsm4(qbase + ks * 32,             qh0, qh1, qh2, qh3);
            ldsm4(qbase + (OQL-OQH) + ks * 32, ql0, ql1, ql2, ql3);
            uint32_t bh0,bh1,bh2,bh3, bl0,bl1,bl2,bl3;
            ldsm4(kbase + ks * 32,             bh0, bh1, bh2, bh3);
            ldsm4(kbase + (OKL-OKH) + ks * 32, bl0, bl1, bl2, bl3);
            mma16816(sf0, qh0,qh1,qh2,qh3, bh0,bh1);
            mma16816(sf0, qh0,qh1,qh2,qh3, bl0,bl1);
            mma16816(sf0, ql0,ql1,ql2,ql3, bh0,bh1);
            mma16816(sf1, qh0,qh1,qh2,qh3, bh2,bh3);
            mma16816(sf1, qh0,qh1,qh2,qh3, bl2,bl3);
            mma16816(sf1, ql0,ql1,ql2,ql3, bh2,bh3);
        }

        if (lt == nloc - 1) {
            int c0 = kstart + lt * BN + wh * 16 + 2 * (lane & 3);
            if (c0     >= kend) { sf0[0] = NEGV; sf0[2] = NEGV; }
            if (c0 + 1 >= kend) { sf0[1] = NEGV; sf0[3] = NEGV; }
            if (c0 + 8 >= kend) { sf1[0] = NEGV; sf1[2] = NEGV; }
            if (c0 + 9 >= kend) { sf1[1] = NEGV; sf1[3] = NEGV; }
        }

        float pm0 = fmaxf(fmaxf(sf0[0], sf0[1]), fmaxf(sf1[0], sf1[1]));
        float pm1 = fmaxf(fmaxf(sf0[2], sf0[3]), fmaxf(sf1[2], sf1[3]));
        pm0 = fmaxf(pm0, __shfl_xor_sync(0xffffffffu, pm0, 1));
        pm0 = fmaxf(pm0, __shfl_xor_sync(0xffffffffu, pm0, 2));
        pm1 = fmaxf(pm1, __shfl_xor_sync(0xffffffffu, pm1, 1));
        pm1 = fmaxf(pm1, __shfl_xor_sync(0xffffffffu, pm1, 2));
        if ((lane & 3) == 0) {
            sM[wh * 64 + row0]     = pm0;
            sM[wh * 64 + row0 + 8] = pm1;
        }
        __syncthreads();   /* S1: scores done, m exchanged, sK free */

        if (pf) {
            #pragma unroll
            for (int j = 0; j < 4; j++) {
                int idx = tid * 4 + j * (NTH * 4);
                int r = idx >> 7, c = idx & (HD - 1);
                uint32_t h0, l0, h1, l1;
                split2(kreg[j].x, kreg[j].y, h0, l0);
                split2(kreg[j].z, kreg[j].w, h1, l1);
                *(uint2*)(smc + OKH + r * TSB + c * 2) = make_uint2(h0, h1);
                *(uint2*)(smc + OKL + r * TSB + c * 2) = make_uint2(l0, l1);
            }
        }

        float om0 = sM[(wh ^ 1) * 64 + row0];
        float om1 = sM[(wh ^ 1) * 64 + row0 + 8];
        float mn0 = fmaxf(m0r, fmaxf(pm0, om0));
        float mn1 = fmaxf(m1r, fmaxf(pm1, om1));
        float a0 = __expf(m0r - mn0);
        float a1 = __expf(m1r - mn1);
        m0r = mn0; m1r = mn1;
        float p00 = __expf(sf0[0] - mn0), p01 = __expf(sf0[1] - mn0);
        float p08 = __expf(sf1[0] - mn0), p09 = __expf(sf1[1] - mn0);
        float p10 = __expf(sf0[2] - mn1), p11 = __expf(sf0[3] - mn1);
        float p18 = __expf(sf1[2] - mn1), p19 = __expf(sf1[3] - mn1);
        float ls0 = p00 + p01 + p08 + p09;
        float ls1 = p10 + p11 + p18 + p19;
        ls0 += __shfl_xor_sync(0xffffffffu, ls0, 1);
        ls0 += __shfl_xor_sync(0xffffffffu, ls0, 2);
        ls1 += __shfl_xor_sync(0xffffffffu, ls1, 1);
        ls1 += __shfl_xor_sync(0xffffffffu, ls1, 2);
        l0r = l0r * a0 + ls0;
        l1r = l1r * a1 + ls1;

        {
            uint32_t h, l;
            char* pr0 = smc + OPH + row0 * PSB + (wh * 16 + 2 * (lane & 3)) * 2;
            char* pr1 = pr0 + 8 * PSB;
            split2(p00, p01, h, l);
            *(uint32_t*)(pr0)                    = h;
            *(uint32_t*)(pr0 + (OPL - OPH))      = l;
            split2(p08, p09, h, l);
            *(uint32_t*)(pr0 + 16)               = h;
            *(uint32_t*)(pr0 + 16 + (OPL - OPH)) = l;
            split2(p10, p11, h, l);
            *(uint32_t*)(pr1)                    = h;
            *(uint32_t*)(pr1 + (OPL - OPH))      = l;
            split2(p18, p19, h, l);
            *(uint32_t*)(pr1 + 16)               = h;
            *(uint32_t*)(pr1 + 16 + (OPL - OPH)) = l;
        }

        #pragma unroll
        for (int nt = 0; nt < 8; nt++) {
            of[nt][0] *= a0; of[nt][1] *= a0;
            of[nt][2] *= a1; of[nt][3] *= a1;
        }
        __syncthreads();   /* S2: full-width P ready */

        #pragma unroll
        for (int ks = 0; ks < 2; ks++) {
            uint32_t ph0,ph1,ph2,ph3, pl0,pl1,pl2,pl3;
            ldsm4(pbase + ks * 32,             ph0, ph1, ph2, ph3);
            ldsm4(pbase + (OPL-OPH) + ks * 32, pl0, pl1, pl2, pl3);
            #pragma unroll
            for (int ntp = 0; ntp < 4; ntp++) {
                uint32_t vh0,vh1,vh2,vh3, vl0,vl1,vl2,vl3;
                uint32_t va = vbase + ks * (16 * TSB) + ntp * 32;
                ldsm4t(va,              vh0, vh1, vh2, vh3);
                ldsm4t(va + (OVL-OVH),  vl0, vl1, vl2, vl3);
                mma16816(of[ntp*2],   ph0,ph1,ph2,ph3, vh0,vh1);
                mma16816(of[ntp*2],   ph0,ph1,ph2,ph3, vl0,vl1);
                mma16816(of[ntp*2],   pl0,pl1,pl2,pl3, vh0,vh1);
                mma16816(of[ntp*2+1], ph0,ph1,ph2,ph3, vh2,vh3);
                mma16816(of[ntp*2+1], ph0,ph1,ph2,ph3, vl2,vl3);
                mma16816(of[ntp*2+1], pl0,pl1,pl2,pl3, vh2,vh3);
            }
        }
        __syncthreads();   /* S3: sV free */

        if (pf) {
            #pragma unroll
            for (int j = 0; j < 4; j++) {
                int idx = tid * 4 + j * (NTH * 4);
                int r = idx >> 7, c = idx & (HD - 1);
                uint32_t h0, l0, h1, l1;
                split2(vreg[j].x, vreg[j].y, h0, l0);
                split2(vreg[j].z, vreg[j].w, h1, l1);
                *(uint2*)(smc + OVH + r * TSB + c * 2) = make_uint2(h0, h1);
                *(uint2*)(smc + OVL + r * TSB + c * 2) = make_uint2(l0, l1);
            }
        }
    }

    /* ---- epilogue: write unnormalized partials + (m, l) ---- */
    if ((lane & 3) == 0) {
        sM[wh * 64 + row0]     = l0r;
        sM[wh * 64 + row0 + 8] = l1r;
    }
    __syncthreads();
    {
        const long slot = ((long)(b * 32 + qb) * NCH + ch);
        float* po = g_po + slot * BM * HD;
        float lj0 = l0r + sM[(wh ^ 1) * 64 + row0];
        float lj1 = l1r + sM[(wh ^ 1) * 64 + row0 + 8];
        if (wh == 0 && (lane & 3) == 0) {
            g_pm[slot * BM + row0]     = m0r;
            g_pm[slot * BM + row0 + 8] = m1r;
            g_pl[slot * BM + row0]     = lj0;
            g_pl[slot * BM + row0 + 8] = lj1;
        }
        float* o0 = po + row0 * HD + wh * 64 + 2 * (lane & 3);
        #pragma unroll
        for (int nt = 0; nt < 8; nt++) {
            *(float2*)(o0 + nt * 8)          = make_float2(of[nt][0], of[nt][1]);
            *(float2*)(o0 + 8 * HD + nt * 8) = make_float2(of[nt][2], of[nt][3]);
        }
    }
}

/* ---------------- kernel 2: combine partials + mean rows ---------------- */
__global__ __launch_bounds__(NTH)
void combine_kernel(const float* __restrict__ V, const int* __restrict__ LENS,
                    float* __restrict__ OUT)
{
    __shared__ float scr[3 * HD];
    const int b   = blockIdx.y;
    const int qb  = blockIdx.x;
    const int q0  = qb * BM;
    const int len = LENS[b];
    const int tid = threadIdx.x;

    const float* vb = V + (long)b * SEQ * HD;
    float*       ob = OUT + ((long)b * SEQ + q0) * HD;

    /* ---- attention rows: merge up to NCH chunk partials ---- */
    int nrows = len - q0; if (nrows > BM) nrows = BM; if (nrows < 0) nrows = 0;
    const int nch = (len + CHK - 1) / CHK;
    const int r    = tid >> 2;            /* 4 threads per row */
    const int cseg = (tid & 3) * 32;
    if (r < nrows) {
        const long slot0 = (long)(b * 32 + qb) * NCH;
        float mv[NCH], w[NCH];
        float mstar = -INFINITY;
        #pragma unroll
        for (int c = 0; c < NCH; c++) {
            mv[c] = (c < nch) ? g_pm[(slot0 + c) * BM + r] : -INFINITY;
            mstar = fmaxf(mstar, mv[c]);
        }
        float lsum = 0.f;
        #pragma unroll
        for (int c = 0; c < NCH; c++) {
            w[c] = __expf(mv[c] - mstar);            /* inactive -> 0 */
            lsum += w[c] * g_pl[(slot0 + c) * BM + r]; /* inactive slot = 0.0 */
        }
        const float inv = 1.0f / lsum;
        const float* po = g_po + slot0 * BM * HD + (long)r * HD + cseg;
        float* orow = ob + (long)r * HD + cseg;
        #pragma unroll
        for (int j = 0; j < 8; j++) {
            float4 acc = make_float4(0.f, 0.f, 0.f, 0.f);
            #pragma unroll
            for (int c = 0; c < NCH; c++) {
                float4 t = *(const float4*)(po + (long)c * BM * HD + 4 * j);
                acc.x += w[c] * t.x; acc.y += w[c] * t.y;
                acc.z += w[c] * t.z; acc.w += w[c] * t.w;
            }
            acc.x *= inv; acc.y *= inv; acc.z *= inv; acc.w *= inv;
            *(float4*)(orow + 4 * j) = acc;
        }
    }

    /* ---- fully-masked rows: uniform softmax -> mean(v[b]) ---- */
    if (q0 + BM > len) {
        const int c    = tid & (HD - 1);
        const int part = tid >> 7;
        float a0 = 0.f, a1 = 0.f, a2 = 0.f, a3 = 0.f;
        const float* vp = vb + (long)part * HD + c;
        for (int s = 0; s < SEQ / 2; s += 4) {
            a0 += vp[(long)(s + 0) * 2 * HD];
            a1 += vp[(long)(s + 1) * 2 * HD];
            a2 += vp[(long)(s + 2) * 2 * HD];
            a3 += vp[(long)(s + 3) * 2 * HD];
        }
        scr[part * HD + c] = (a0 + a1) + (a2 + a3);
        __syncthreads();
        if (tid < HD) scr[2 * HD + tid] = (scr[tid] + scr[HD + tid]) * (1.0f / SEQ);
        __syncthreads();
        int rstart = len - q0; if (rstart < 0) rstart = 0;
        for (int idx = tid; idx < (BM - rstart) * HD; idx += NTH) {
            int rr = rstart + (idx >> 7);
            int cc = idx & (HD - 1);
            ob[rr * HD + cc] = scr[2 * HD + cc];
        }
    }
}

extern "C" void kernel_launch(void* const* d_in, const int* in_sizes, int n_in,
                              void* d_out, int out_size)
{
    const float* q    = (const float*)d_in[0];
    const float* k    = (const float*)d_in[1];
    const float* v    = (const float*)d_in[2];
    const int*   lens = (const int*)d_in[3];
    float*       out  = (float*)d_out;

    cudaFuncSetAttribute(attn_part_kernel,
                         cudaFuncAttributeMaxDynamicSharedMemorySize, SMBYTES);

    dim3 g1(SEQ / BM, NB, NCH);     /* 32 x 8 x 4 = 1024 CTAs, <=16 iters each */
    attn_part_kernel<<<g1, NTH, SMBYTES>>>(q, k, v, lens);

    dim3 g2(SEQ / BM, NB);          /* 256 CTAs */
    combine_kernel<<<g2, NTH>>>(v, lens, out);
}

// round 14
// speedup vs baseline: 2.9135x; 1.1080x over previous
#include <cuda_runtime.h>
#include <cuda_bf16.h>
#include <stdint.h>
#include <math.h>

#define NB   8
#define SEQ  2048
#define HD   128
#define BM   64
#define BN   32
#define NCH  4        /* key chunks of 512 */
#define CHK  512
#define NTH  256
#define TSB  272      /* Q/K/V bf16 row stride BYTES (256 data + 16 pad) */
#define PSB  80       /* P bf16 row stride BYTES (64 data + 16 pad) */
#define NEGV (-1.0e9f)

/* smem byte offsets (ping-pong K/V) */
#define OQH  0
#define OQL  17408
#define OK0H 34816
#define OK0L 43520
#define OV0H 52224
#define OV0L 60928
#define BUFSZ 34816   /* one K/V buffer set (4 x 8704) */
#define OPH  104448
#define OPL  109568
#define ORED 114688   /* 128 floats exactly -> ends at SMBYTES */
#define SMBYTES 115200

/* split-K scratch: zero-initialized device globals (never-written slots stay 0) */
__device__ float g_po[(long)NB * 32 * NCH * BM * HD];  /* unnormalized O partials */
__device__ float g_pm[NB * 32 * NCH * BM];             /* row max */
__device__ float g_pl[NB * 32 * NCH * BM];             /* row sum */
__device__ float g_msum[NB * 8 * HD];                  /* V slice sums (8 x 256 rows) */

__device__ __forceinline__ uint32_t smaddr(const void* p) {
    return (uint32_t)__cvta_generic_to_shared(p);
}
__device__ __forceinline__ void ldsm4(uint32_t a, uint32_t& r0, uint32_t& r1,
                                      uint32_t& r2, uint32_t& r3) {
    asm volatile("ldmatrix.sync.aligned.m8n8.x4.shared.b16 {%0,%1,%2,%3}, [%4];"
                 : "=r"(r0), "=r"(r1), "=r"(r2), "=r"(r3) : "r"(a));
}
__device__ __forceinline__ void ldsm4t(uint32_t a, uint32_t& r0, uint32_t& r1,
                                       uint32_t& r2, uint32_t& r3) {
    asm volatile("ldmatrix.sync.aligned.m8n8.x4.trans.shared.b16 {%0,%1,%2,%3}, [%4];"
                 : "=r"(r0), "=r"(r1), "=r"(r2), "=r"(r3) : "r"(a));
}
__device__ __forceinline__ void mma16816(float* c, uint32_t a0, uint32_t a1, uint32_t a2,
                                         uint32_t a3, uint32_t b0, uint32_t b1) {
    asm volatile("mma.sync.aligned.m16n8k16.row.col.f32.bf16.bf16.f32 "
                 "{%0,%1,%2,%3}, {%4,%5,%6,%7}, {%8,%9}, {%0,%1,%2,%3};"
                 : "+f"(c[0]), "+f"(c[1]), "+f"(c[2]), "+f"(c[3])
                 : "r"(a0), "r"(a1), "r"(a2), "r"(a3), "r"(b0), "r"(b1));
}
__device__ __forceinline__ void split2(float x0, float x1, uint32_t& h, uint32_t& l) {
    __nv_bfloat16 h0 = __float2bfloat16_rn(x0);
    __nv_bfloat16 h1 = __float2bfloat16_rn(x1);
    h = (uint32_t)__bfloat16_as_ushort(h0) | ((uint32_t)__bfloat16_as_ushort(h1) << 16);
    float r0 = x0 - __bfloat162float(h0);
    float r1 = x1 - __bfloat162float(h1);
    __nv_bfloat16 l0 = __float2bfloat16_rn(r0);
    __nv_bfloat16 l1 = __float2bfloat16_rn(r1);
    l = (uint32_t)__bfloat16_as_ushort(l0) | ((uint32_t)__bfloat16_as_ushort(l1) << 16);
}

/* ---------- kernel 1: per-chunk flash partials + concurrent V slice sums ---------- */
__global__ __launch_bounds__(NTH, 2)
void attn_part_kernel(const float* __restrict__ Q, const float* __restrict__ K,
                      const float* __restrict__ V, const int* __restrict__ LENS)
{
    extern __shared__ char smc[];
    const uint32_t smb = smaddr(smc);
    float* sM = (float*)(smc + ORED);

    const int b   = blockIdx.y;
    const int qb  = blockIdx.x;
    const int tid = threadIdx.x;

    /* ---- concurrent lane: V slice sums for the mean path ----
       scratch lives at smc+0 (Q region, unused here); ORED is only 512B. */
    if (blockIdx.z == NCH) {
        if (qb < 8) {
            float* scr = (float*)smc;    /* 256 floats, well inside 17KB Q region */
            const int c    = tid & (HD - 1);
            const int part = tid >> 7;   /* 0/1 */
            const float* vp = V + ((long)b * SEQ + qb * 256 + part) * HD + c;
            float a0 = 0.f, a1 = 0.f, a2 = 0.f, a3 = 0.f;
            #pragma unroll 4
            for (int s = 0; s < 128; s += 4) {
                a0 += vp[(long)(s + 0) * 2 * HD];
                a1 += vp[(long)(s + 1) * 2 * HD];
                a2 += vp[(long)(s + 2) * 2 * HD];
                a3 += vp[(long)(s + 3) * 2 * HD];
            }
            scr[part * HD + c] = (a0 + a1) + (a2 + a3);
            __syncthreads();
            if (tid < HD)
                g_msum[(b * 8 + qb) * HD + tid] = scr[tid] + scr[HD + tid];
        }
        return;
    }

    const int q0   = qb * BM;
    const int ch   = blockIdx.z;
    const int len  = LENS[b];
    const int kstart = ch * CHK;
    if (q0 >= len || kstart >= len) return;
    const int kend = (len < kstart + CHK) ? len : (kstart + CHK);

    const int wid  = tid >> 5;
    const int lane = tid & 31;
    const int wr = wid & 3;
    const int wh = wid >> 2;
    const int rq = lane >> 2;
    const int row0 = wr * 16 + rq;

    const float* qbp = Q + ((long)b * SEQ + q0) * HD;
    const float* kb  = K + (long)b * SEQ * HD;
    const float* vb  = V + (long)b * SEQ * HD;

    /* ---- stage Q (pre-scaled), split hi/lo ---- */
    const float scale = 0.088388347648318447f;
    for (int idx = tid * 4; idx < BM * HD; idx += NTH * 4) {
        float4 t = *(const float4*)(qbp + idx);
        int r = idx >> 7, c = idx & (HD - 1);
        uint32_t h0, l0, h1, l1;
        split2(t.x * scale, t.y * scale, h0, l0);
        split2(t.z * scale, t.w * scale, h1, l1);
        *(uint2*)(smc + OQH + r * TSB + c * 2) = make_uint2(h0, h1);
        *(uint2*)(smc + OQL + r * TSB + c * 2) = make_uint2(l0, l1);
    }
    /* ---- stage first K/V tile into buffer 0 ---- */
    {
        const float* kbt = kb + (long)kstart * HD;
        const float* vbt = vb + (long)kstart * HD;
        for (int idx = tid * 4; idx < BN * HD; idx += NTH * 4) {
            int r = idx >> 7, c = idx & (HD - 1);
            float4 t = *(const float4*)(kbt + idx);
            uint32_t h0, l0, h1, l1;
            split2(t.x, t.y, h0, l0); split2(t.z, t.w, h1, l1);
            *(uint2*)(smc + OK0H + r * TSB + c * 2) = make_uint2(h0, h1);
            *(uint2*)(smc + OK0L + r * TSB + c * 2) = make_uint2(l0, l1);
            t = *(const float4*)(vbt + idx);
            split2(t.x, t.y, h0, l0); split2(t.z, t.w, h1, l1);
            *(uint2*)(smc + OV0H + r * TSB + c * 2) = make_uint2(h0, h1);
            *(uint2*)(smc + OV0L + r * TSB + c * 2) = make_uint2(l0, l1);
        }
    }

    const uint32_t qbase = smb + OQH + (wr * 16 + (lane & 15)) * TSB + ((lane >> 4) << 4);
    const uint32_t kbase = smb + OK0H + (wh * 16 + (lane & 7) + ((lane >> 4) << 3)) * TSB
                               + (((lane >> 3) & 1) << 4);
    const uint32_t pbase = smb + OPH + (wr * 16 + (lane & 15)) * PSB + ((lane >> 4) << 4);
    const uint32_t vbase = smb + OV0H + (lane & 15) * TSB + ((lane >> 4) << 4) + wh * 128;

    float of[8][4];
    #pragma unroll
    for (int i = 0; i < 8; i++)
        of[i][0] = of[i][1] = of[i][2] = of[i][3] = 0.f;
    float m0r = -INFINITY, m1r = -INFINITY, l0r = 0.f, l1r = 0.f;

    __syncthreads();

    int p = 0;
    const int nloc = (kend - kstart + BN - 1) / BN;
    for (int lt = 0; lt < nloc; lt++) {
        float4 kreg[4], vreg[4];
        const bool pf = (lt + 1 < nloc);
        if (pf) {
            const float* kbt = kb + (long)(kstart + (lt + 1) * BN) * HD;
            const float* vbt = vb + (long)(kstart + (lt + 1) * BN) * HD;
            #pragma unroll
            for (int j = 0; j < 4; j++) {
                int idx = tid * 4 + j * (NTH * 4);
                kreg[j] = *(const float4*)(kbt + idx);
                vreg[j] = *(const float4*)(vbt + idx);
            }
        }
        const uint32_t pofs = (uint32_t)p * BUFSZ;

        /* ---- scores from buf[p] (prefetch latency hidden behind MMAs) ---- */
        float sf0[4] = {0.f,0.f,0.f,0.f};
        float sf1[4] = {0.f,0.f,0.f,0.f};
        #pragma unroll
        for (int ks = 0; ks < 8; ks++) {
            uint32_t qh0,qh1,qh2,qh3, ql0,ql1,ql2,ql3;
            ldsm4(qbase + ks * 32,             qh0, qh1, qh2, qh3);
            ldsm4(qbase + (OQL-OQH) + ks * 32, ql0, ql1, ql2, ql3);
            uint32_t bh0,bh1,bh2,bh3, bl0,bl1,bl2,bl3;
            ldsm4(kbase + pofs + ks * 32,               bh0, bh1, bh2, bh3);
            ldsm4(kbase + pofs + (OK0L-OK0H) + ks * 32, bl0, bl1, bl2, bl3);
            mma16816(sf0, qh0,qh1,qh2,qh3, bh0,bh1);
            mma16816(sf0, qh0,qh1,qh2,qh3, bl0,bl1);
            mma16816(sf0, ql0,ql1,ql2,ql3, bh0,bh1);
            mma16816(sf1, qh0,qh1,qh2,qh3, bh2,bh3);
            mma16816(sf1, qh0,qh1,qh2,qh3, bl2,bl3);
            mma16816(sf1, ql0,ql1,ql2,ql3, bh2,bh3);
        }

        if (lt == nloc - 1) {
            int c0 = kstart + lt * BN + wh * 16 + 2 * (lane & 3);
            if (c0     >= kend) { sf0[0] = NEGV; sf0[2] = NEGV; }
            if (c0 + 1 >= kend) { sf0[1] = NEGV; sf0[3] = NEGV; }
            if (c0 + 8 >= kend) { sf1[0] = NEGV; sf1[2] = NEGV; }
            if (c0 + 9 >= kend) { sf1[1] = NEGV; sf1[3] = NEGV; }
        }

        float pm0 = fmaxf(fmaxf(sf0[0], sf0[1]), fmaxf(sf1[0], sf1[1]));
        float pm1 = fmaxf(fmaxf(sf0[2], sf0[3]), fmaxf(sf1[2], sf1[3]));
        pm0 = fmaxf(pm0, __shfl_xor_sync(0xffffffffu, pm0, 1));
        pm0 = fmaxf(pm0, __shfl_xor_sync(0xffffffffu, pm0, 2));
        pm1 = fmaxf(pm1, __shfl_xor_sync(0xffffffffu, pm1, 1));
        pm1 = fmaxf(pm1, __shfl_xor_sync(0xffffffffu, pm1, 2));
        if ((lane & 3) == 0) {
            sM[wh * 64 + row0]     = pm0;
            sM[wh * 64 + row0 + 8] = pm1;
        }
        __syncthreads();   /* S1: m exchanged; prior-iter PV P-reads + buf[p^1] V-reads done */

        /* stage next tile into the idle buffer (visible after S2) */
        if (pf) {
            const uint32_t nofs = (uint32_t)(p ^ 1) * BUFSZ;
            #pragma unroll
            for (int j = 0; j < 4; j++) {
                int idx = tid * 4 + j * (NTH * 4);
                int r = idx >> 7, c = idx & (HD - 1);
                uint32_t h0, l0, h1, l1;
                split2(kreg[j].x, kreg[j].y, h0, l0);
                split2(kreg[j].z, kreg[j].w, h1, l1);
                *(uint2*)(smc + OK0H + nofs + r * TSB + c * 2) = make_uint2(h0, h1);
                *(uint2*)(smc + OK0L + nofs + r * TSB + c * 2) = make_uint2(l0, l1);
                split2(vreg[j].x, vreg[j].y, h0, l0);
                split2(vreg[j].z, vreg[j].w, h1, l1);
                *(uint2*)(smc + OV0H + nofs + r * TSB + c * 2) = make_uint2(h0, h1);
                *(uint2*)(smc + OV0L + nofs + r * TSB + c * 2) = make_uint2(l0, l1);
            }
        }

        float om0 = sM[(wh ^ 1) * 64 + row0];
        float om1 = sM[(wh ^ 1) * 64 + row0 + 8];
        float mn0 = fmaxf(m0r, fmaxf(pm0, om0));
        float mn1 = fmaxf(m1r, fmaxf(pm1, om1));
        float a0 = __expf(m0r - mn0);
        float a1 = __expf(m1r - mn1);
        m0r = mn0; m1r = mn1;
        float p00 = __expf(sf0[0] - mn0), p01 = __expf(sf0[1] - mn0);
        float p08 = __expf(sf1[0] - mn0), p09 = __expf(sf1[1] - mn0);
        float p10 = __expf(sf0[2] - mn1), p11 = __expf(sf0[3] - mn1);
        float p18 = __expf(sf1[2] - mn1), p19 = __expf(sf1[3] - mn1);
        float ls0 = p00 + p01 + p08 + p09;
        float ls1 = p10 + p11 + p18 + p19;
        ls0 += __shfl_xor_sync(0xffffffffu, ls0, 1);
        ls0 += __shfl_xor_sync(0xffffffffu, ls0, 2);
        ls1 += __shfl_xor_sync(0xffffffffu, ls1, 1);
        ls1 += __shfl_xor_sync(0xffffffffu, ls1, 2);
        l0r = l0r * a0 + ls0;
        l1r = l1r * a1 + ls1;

        {
            uint32_t h, l;
            char* pr0 = smc + OPH + row0 * PSB + (wh * 16 + 2 * (lane & 3)) * 2;
            char* pr1 = pr0 + 8 * PSB;
            split2(p00, p01, h, l);
            *(uint32_t*)(pr0)                    = h;
            *(uint32_t*)(pr0 + (OPL - OPH))      = l;
            split2(p08, p09, h, l);
            *(uint32_t*)(pr0 + 16)               = h;
            *(uint32_t*)(pr0 + 16 + (OPL - OPH)) = l;
            split2(p10, p11, h, l);
            *(uint32_t*)(pr1)                    = h;
            *(uint32_t*)(pr1 + (OPL - OPH))      = l;
            split2(p18, p19, h, l);
            *(uint32_t*)(pr1 + 16)               = h;
            *(uint32_t*)(pr1 + 16 + (OPL - OPH)) = l;
        }

        #pragma unroll
        for (int nt = 0; nt < 8; nt++) {
            of[nt][0] *= a0; of[nt][1] *= a0;
            of[nt][2] *= a1; of[nt][3] *= a1;
        }
        __syncthreads();   /* S2: P + next-tile staging visible */

        /* ---- O += P @ V from buf[p] ---- */
        #pragma unroll
        for (int ks = 0; ks < 2; ks++) {
            uint32_t ph0,ph1,ph2,ph3, pl0,pl1,pl2,pl3;
            ldsm4(pbase + ks * 32,             ph0, ph1, ph2, ph3);
            ldsm4(pbase + (OPL-OPH) + ks * 32, pl0, pl1, pl2, pl3);
            #pragma unroll
            for (int ntp = 0; ntp < 4; ntp++) {
                uint32_t vh0,vh1,vh2,vh3, vl0,vl1,vl2,vl3;
                uint32_t va = vbase + pofs + ks * (16 * TSB) + ntp * 32;
                ldsm4t(va,               vh0, vh1, vh2, vh3);
                ldsm4t(va + (OV0L-OV0H), vl0, vl1, vl2, vl3);
                mma16816(of[ntp*2],   ph0,ph1,ph2,ph3, vh0,vh1);
                mma16816(of[ntp*2],   ph0,ph1,ph2,ph3, vl0,vl1);
                mma16816(of[ntp*2],   pl0,pl1,pl2,pl3, vh0,vh1);
                mma16816(of[ntp*2+1], ph0,ph1,ph2,ph3, vh2,vh3);
                mma16816(of[ntp*2+1], ph0,ph1,ph2,ph3, vl2,vl3);
                mma16816(of[ntp*2+1], pl0,pl1,pl2,pl3, vh2,vh3);
            }
        }
        p ^= 1;
    }

    /* ---- epilogue: write unnormalized partials + (m, l) ---- */
    if ((lane & 3) == 0) {
        sM[wh * 64 + row0]     = l0r;
        sM[wh * 64 + row0 + 8] = l1r;
    }
    __syncthreads();
    {
        const long slot = ((long)(b * 32 + qb) * NCH + ch);
        float* po = g_po + slot * BM * HD;
        float lj0 = l0r + sM[(wh ^ 1) * 64 + row0];
        float lj1 = l1r + sM[(wh ^ 1) * 64 + row0 + 8];
        if (wh == 0 && (lane & 3) == 0) {
            g_pm[slot * BM + row0]     = m0r;
            g_pm[slot * BM + row0 + 8] = m1r;
            g_pl[slot * BM + row0]     = lj0;
            g_pl[slot * BM + row0 + 8] = lj1;
        }
        float* o0 = po + row0 * HD + wh * 64 + 2 * (lane & 3);
        #pragma unroll
        for (int nt = 0; nt < 8; nt++) {
            *(float2*)(o0 + nt * 8)          = make_float2(of[nt][0], of[nt][1]);
            *(float2*)(o0 + 8 * HD + nt * 8) = make_float2(of[nt][2], of[nt][3]);
        }
    }
}

/* ---------------- kernel 2: combine partials + mean rows ---------------- */
__global__ __launch_bounds__(NTH)
void combine_kernel(const int* __restrict__ LENS, float* __restrict__ OUT)
{
    __shared__ float scr[HD];
    const int b   = blockIdx.y;
    const int qb  = blockIdx.x;
    const int q0  = qb * BM;
    const int len = LENS[b];
    const int tid = threadIdx.x;

    float* ob = OUT + ((long)b * SEQ + q0) * HD;

    /* ---- attention rows: merge up to NCH chunk partials ---- */
    int nrows = len - q0; if (nrows > BM) nrows = BM; if (nrows < 0) nrows = 0;
    const int nch  = (len + CHK - 1) / CHK;
    const int r    = tid >> 2;           /* 4 threads per row */
    const int cseg = (tid & 3) * 32;
    if (r < nrows) {
        const long slot0 = (long)(b * 32 + qb) * NCH;
        float mv[NCH], w[NCH];
        float mstar = -INFINITY;
        #pragma unroll
        for (int c = 0; c < NCH; c++) {
            mv[c] = (c < nch) ? g_pm[(slot0 + c) * BM + r] : -INFINITY;
            mstar = fmaxf(mstar, mv[c]);
        }
        float lsum = 0.f;
        #pragma unroll
        for (int c = 0; c < NCH; c++) {
            w[c] = __expf(mv[c] - mstar);              /* inactive -> 0 */
            lsum += w[c] * g_pl[(slot0 + c) * BM + r]; /* inactive slot = 0.0 */
        }
        const float inv = 1.0f / lsum;
        const float* po = g_po + slot0 * BM * HD + (long)r * HD + cseg;
        float* orow = ob + (long)r * HD + cseg;
        #pragma unroll
        for (int j = 0; j < 8; j++) {
            float4 acc = make_float4(0.f, 0.f, 0.f, 0.f);
            #pragma unroll
            for (int c = 0; c < NCH; c++) {
                float4 t = *(const float4*)(po + (long)c * BM * HD + 4 * j);
                acc.x += w[c] * t.x; acc.y += w[c] * t.y;
                acc.z += w[c] * t.z; acc.w += w[c] * t.w;
            }
            acc.x *= inv; acc.y *= inv; acc.z *= inv; acc.w *= inv;
            *(float4*)(orow + 4 * j) = acc;
        }
    }

    /* ---- fully-masked rows: uniform softmax -> mean(v[b]) from slice sums ---- */
    if (q0 + BM > len) {
        if (tid < HD) {
            float s = 0.f;
            #pragma unroll
            for (int sl = 0; sl < 8; sl++)
                s += g_msum[(b * 8 + sl) * HD + tid];
            scr[tid] = s * (1.0f / SEQ);
        }
        __syncthreads();
        int rstart = len - q0; if (rstart < 0) rstart = 0;
        for (int idx = tid; idx < (BM - rstart) * HD; idx += NTH) {
            int rr = rstart + (idx >> 7);
            int cc = idx & (HD - 1);
            ob[rr * HD + cc] = scr[cc];
        }
    }
}

extern "C" void kernel_launch(void* const* d_in, const int* in_sizes, int n_in,
                              void* d_out, int out_size)
{
    const float* q    = (const float*)d_in[0];
    const float* k    = (const float*)d_in[1];
    const float* v    = (const float*)d_in[2];
    const int*   lens = (const int*)d_in[3];
    float*       out  = (float*)d_out;

    cudaFuncSetAttribute(attn_part_kernel,
                         cudaFuncAttributeMaxDynamicSharedMemorySize, SMBYTES);

    dim3 g1(SEQ / BM, NB, NCH + 1);   /* z==NCH lane computes V slice sums concurrently */
    attn_part_kernel<<<g1, NTH, SMBYTES>>>(q, k, v, lens);

    dim3 g2(SEQ / BM, NB);
    combine_kernel<<<g2, NTH>>>(lens, out);
}

// round 17
// speedup vs baseline: 3.3970x; 1.1660x over previous
#include <cuda_runtime.h>
#include <cuda_bf16.h>
#include <stdint.h>
#include <math.h>

#define NB   8
#define SEQ  2048
#define HD   128
#define BM   64
#define BN   32
#define NCH  4        /* key chunks of 512 */
#define CHK  512
#define NTH  256
#define TSB  272      /* Q/K/V bf16 tile row stride BYTES (256 data + 16 pad) */
#define PSB  80       /* P bf16 row stride BYTES (64 data + 16 pad) */
#define NEGV (-1.0e9f)

/* smem byte offsets (ping-pong K/V) */
#define OQH  0
#define OQL  17408
#define OK0H 34816
#define OK0L 43520
#define OV0H 52224
#define OV0L 60928
#define BUFSZ 34816   /* one K/V buffer set (4 x 8704) */
#define OPH  104448
#define OPL  109568
#define ORED 114688   /* 128 floats exactly -> ends at SMBYTES */
#define SMBYTES 115200

/* 64-thread pair barrier (warps (wr,0),(wr,1)); ids 1..4 (0 = __syncthreads) */
#define BARP(wr_) asm volatile("bar.sync %0, 64;" :: "r"((wr_) + 1) : "memory")

/* split-K scratch: zero-initialized device globals (never-written slots stay 0) */
__device__ float g_po[(long)NB * 32 * NCH * BM * HD];  /* unnormalized O partials */
__device__ float g_pm[NB * 32 * NCH * BM];             /* row max */
__device__ float g_pl[NB * 32 * NCH * BM];             /* row sum */
__device__ float g_msum[NB * 8 * HD];                  /* V slice sums */

__device__ __forceinline__ uint32_t smaddr(const void* p) {
    return (uint32_t)__cvta_generic_to_shared(p);
}
__device__ __forceinline__ void ldsm4(uint32_t a, uint32_t& r0, uint32_t& r1,
                                      uint32_t& r2, uint32_t& r3) {
    asm volatile("ldmatrix.sync.aligned.m8n8.x4.shared.b16 {%0,%1,%2,%3}, [%4];"
                 : "=r"(r0), "=r"(r1), "=r"(r2), "=r"(r3) : "r"(a));
}
__device__ __forceinline__ void ldsm4t(uint32_t a, uint32_t& r0, uint32_t& r1,
                                       uint32_t& r2, uint32_t& r3) {
    asm volatile("ldmatrix.sync.aligned.m8n8.x4.trans.shared.b16 {%0,%1,%2,%3}, [%4];"
                 : "=r"(r0), "=r"(r1), "=r"(r2), "=r"(r3) : "r"(a));
}
__device__ __forceinline__ void mma16816(float* c, uint32_t a0, uint32_t a1, uint32_t a2,
                                         uint32_t a3, uint32_t b0, uint32_t b1) {
    asm volatile("mma.sync.aligned.m16n8k16.row.col.f32.bf16.bf16.f32 "
                 "{%0,%1,%2,%3}, {%4,%5,%6,%7}, {%8,%9}, {%0,%1,%2,%3};"
                 : "+f"(c[0]), "+f"(c[1]), "+f"(c[2]), "+f"(c[3])
                 : "r"(a0), "r"(a1), "r"(a2), "r"(a3), "r"(b0), "r"(b1));
}
/* split two fp32 -> packed hi/lo bf16 words via packed cvt (same rn rounding) */
__device__ __forceinline__ void split2(float x0, float x1, uint32_t& h, uint32_t& l) {
    __nv_bfloat162 hh = __float22bfloat162_rn(make_float2(x0, x1));
    float2 hf = __bfloat1622float2(hh);
    __nv_bfloat162 ll = __float22bfloat162_rn(make_float2(x0 - hf.x, x1 - hf.y));
    h = *reinterpret_cast<uint32_t*>(&hh);
    l = *reinterpret_cast<uint32_t*>(&ll);
}

/* ---------- kernel 1: per-chunk flash partials + concurrent V slice sums ---------- */
__global__ __launch_bounds__(NTH, 2)
void attn_part_kernel(const float* __restrict__ Q, const float* __restrict__ K,
                      const float* __restrict__ V, const int* __restrict__ LENS)
{
    extern __shared__ char smc[];
    const uint32_t smb = smaddr(smc);
    float* sM = (float*)(smc + ORED);

    const int b   = blockIdx.y;
    const int qb  = blockIdx.x;
    const int tid = threadIdx.x;

    /* ---- concurrent lane: V slice sums for the mean path (scratch = Q region) ---- */
    if (blockIdx.z == NCH) {
        if (qb < 8) {
            float* scr = (float*)smc;
            const int c    = tid & (HD - 1);
            const int part = tid >> 7;
            const float* vp = V + ((long)b * SEQ + qb * 256 + part) * HD + c;
            float a0 = 0.f, a1 = 0.f, a2 = 0.f, a3 = 0.f;
            #pragma unroll 4
            for (int s = 0; s < 128; s += 4) {
                a0 += vp[(long)(s + 0) * 2 * HD];
                a1 += vp[(long)(s + 1) * 2 * HD];
                a2 += vp[(long)(s + 2) * 2 * HD];
                a3 += vp[(long)(s + 3) * 2 * HD];
            }
            scr[part * HD + c] = (a0 + a1) + (a2 + a3);
            __syncthreads();
            if (tid < HD)
                g_msum[(b * 8 + qb) * HD + tid] = scr[tid] + scr[HD + tid];
        }
        return;
    }

    const int q0   = qb * BM;
    const int ch   = blockIdx.z;
    const int len  = LENS[b];
    const int kstart = ch * CHK;
    if (q0 >= len || kstart >= len) return;
    const int kend = (len < kstart + CHK) ? len : (kstart + CHK);

    const int wid  = tid >> 5;
    const int lane = tid & 31;
    const int wr = wid & 3;
    const int wh = wid >> 2;
    const int rq = lane >> 2;
    const int row0 = wr * 16 + rq;

    const float* qbp = Q + ((long)b * SEQ + q0) * HD;
    const float* kb  = K + (long)b * SEQ * HD;
    const float* vb  = V + (long)b * SEQ * HD;

    /* ---- stage Q (pre-scaled), split hi/lo ---- */
    const float scale = 0.088388347648318447f;
    for (int idx = tid * 4; idx < BM * HD; idx += NTH * 4) {
        float4 t = *(const float4*)(qbp + idx);
        int r = idx >> 7, c = idx & (HD - 1);
        uint32_t h0, l0, h1, l1;
        split2(t.x * scale, t.y * scale, h0, l0);
        split2(t.z * scale, t.w * scale, h1, l1);
        *(uint2*)(smc + OQH + r * TSB + c * 2) = make_uint2(h0, h1);
        *(uint2*)(smc + OQL + r * TSB + c * 2) = make_uint2(l0, l1);
    }
    /* ---- stage first K/V tile into buffer 0 ---- */
    {
        const float* kbt = kb + (long)kstart * HD;
        const float* vbt = vb + (long)kstart * HD;
        for (int idx = tid * 4; idx < BN * HD; idx += NTH * 4) {
            int r = idx >> 7, c = idx & (HD - 1);
            float4 t = *(const float4*)(kbt + idx);
            uint32_t h0, l0, h1, l1;
            split2(t.x, t.y, h0, l0); split2(t.z, t.w, h1, l1);
            *(uint2*)(smc + OK0H + r * TSB + c * 2) = make_uint2(h0, h1);
            *(uint2*)(smc + OK0L + r * TSB + c * 2) = make_uint2(l0, l1);
            t = *(const float4*)(vbt + idx);
            split2(t.x, t.y, h0, l0); split2(t.z, t.w, h1, l1);
            *(uint2*)(smc + OV0H + r * TSB + c * 2) = make_uint2(h0, h1);
            *(uint2*)(smc + OV0L + r * TSB + c * 2) = make_uint2(l0, l1);
        }
    }

    const uint32_t qbase = smb + OQH + (wr * 16 + (lane & 15)) * TSB + ((lane >> 4) << 4);
    const uint32_t kbase = smb + OK0H + (wh * 16 + (lane & 7) + ((lane >> 4) << 3)) * TSB
                               + (((lane >> 3) & 1) << 4);
    const uint32_t pbase = smb + OPH + (wr * 16 + (lane & 15)) * PSB + ((lane >> 4) << 4);
    const uint32_t vbase = smb + OV0H + (lane & 15) * TSB + ((lane >> 4) << 4) + wh * 128;

    float of[8][4];
    #pragma unroll
    for (int i = 0; i < 8; i++)
        of[i][0] = of[i][1] = of[i][2] = of[i][3] = 0.f;
    float m0r = -INFINITY, m1r = -INFINITY, l0r = 0.f, l1r = 0.f;

    __syncthreads();

    int p = 0;
    const int nloc = (kend - kstart + BN - 1) / BN;
    for (int lt = 0; lt < nloc; lt++) {
        float4 kreg[4], vreg[4];
        const bool pf = (lt + 1 < nloc);
        if (pf) {
            const float* kbt = kb + (long)(kstart + (lt + 1) * BN) * HD;
            const float* vbt = vb + (long)(kstart + (lt + 1) * BN) * HD;
            #pragma unroll
            for (int j = 0; j < 4; j++) {
                int idx = tid * 4 + j * (NTH * 4);
                kreg[j] = *(const float4*)(kbt + idx);
                vreg[j] = *(const float4*)(vbt + idx);
            }
        }
        const uint32_t pofs = (uint32_t)p * BUFSZ;

        /* ---- scores from buf[p] ---- */
        float sf0[4] = {0.f,0.f,0.f,0.f};
        float sf1[4] = {0.f,0.f,0.f,0.f};
        #pragma unroll
        for (int ks = 0; ks < 8; ks++) {
            uint32_t qh0,qh1,qh2,qh3, ql0,ql1,ql2,ql3;
            ldsm4(qbase + ks * 32,             qh0, qh1, qh2, qh3);
            ldsm4(qbase + (OQL-OQH) + ks * 32, ql0, ql1, ql2, ql3);
            uint32_t bh0,bh1,bh2,bh3, bl0,bl1,bl2,bl3;
            ldsm4(kbase + pofs + ks * 32,               bh0, bh1, bh2, bh3);
            ldsm4(kbase + pofs + (OK0L-OK0H) + ks * 32, bl0, bl1, bl2, bl3);
            mma16816(sf0, qh0,qh1,qh2,qh3, bh0,bh1);
            mma16816(sf0, qh0,qh1,qh2,qh3, bl0,bl1);
            mma16816(sf0, ql0,ql1,ql2,ql3, bh0,bh1);
            mma16816(sf1, qh0,qh1,qh2,qh3, bh2,bh3);
            mma16816(sf1, qh0,qh1,qh2,qh3, bl2,bl3);
            mma16816(sf1, ql0,ql1,ql2,ql3, bh2,bh3);
        }

        if (lt == nloc - 1) {
            int c0 = kstart + lt * BN + wh * 16 + 2 * (lane & 3);
            if (c0     >= kend) { sf0[0] = NEGV; sf0[2] = NEGV; }
            if (c0 + 1 >= kend) { sf0[1] = NEGV; sf0[3] = NEGV; }
            if (c0 + 8 >= kend) { sf1[0] = NEGV; sf1[2] = NEGV; }
            if (c0 + 9 >= kend) { sf1[1] = NEGV; sf1[3] = NEGV; }
        }

        float pm0 = fmaxf(fmaxf(sf0[0], sf0[1]), fmaxf(sf1[0], sf1[1]));
        float pm1 = fmaxf(fmaxf(sf0[2], sf0[3]), fmaxf(sf1[2], sf1[3]));
        pm0 = fmaxf(pm0, __shfl_xor_sync(0xffffffffu, pm0, 1));
        pm0 = fmaxf(pm0, __shfl_xor_sync(0xffffffffu, pm0, 2));
        pm1 = fmaxf(pm1, __shfl_xor_sync(0xffffffffu, pm1, 1));
        pm1 = fmaxf(pm1, __shfl_xor_sync(0xffffffffu, pm1, 2));
        if ((lane & 3) == 0) {
            sM[wh * 64 + row0]     = pm0;
            sM[wh * 64 + row0 + 8] = pm1;
        }
        __syncthreads();   /* S1 (full): m exchange + prior staging visible + PV reads done */

        /* stage next tile into the idle buffer (consumed after NEXT full S1) */
        if (pf) {
            const uint32_t nofs = (uint32_t)(p ^ 1) * BUFSZ;
            #pragma unroll
            for (int j = 0; j < 4; j++) {
                int idx = tid * 4 + j * (NTH * 4);
                int r = idx >> 7, c = idx & (HD - 1);
                uint32_t h0, l0, h1, l1;
                split2(kreg[j].x, kreg[j].y, h0, l0);
                split2(kreg[j].z, kreg[j].w, h1, l1);
                *(uint2*)(smc + OK0H + nofs + r * TSB + c * 2) = make_uint2(h0, h1);
                *(uint2*)(smc + OK0L + nofs + r * TSB + c * 2) = make_uint2(l0, l1);
                split2(vreg[j].x, vreg[j].y, h0, l0);
                split2(vreg[j].z, vreg[j].w, h1, l1);
                *(uint2*)(smc + OV0H + nofs + r * TSB + c * 2) = make_uint2(h0, h1);
                *(uint2*)(smc + OV0L + nofs + r * TSB + c * 2) = make_uint2(l0, l1);
            }
        }

        float om0 = sM[(wh ^ 1) * 64 + row0];
        float om1 = sM[(wh ^ 1) * 64 + row0 + 8];
        float mn0 = fmaxf(m0r, fmaxf(pm0, om0));
        float mn1 = fmaxf(m1r, fmaxf(pm1, om1));
        float a0 = __expf(m0r - mn0);
        float a1 = __expf(m1r - mn1);
        m0r = mn0; m1r = mn1;
        float p00 = __expf(sf0[0] - mn0), p01 = __expf(sf0[1] - mn0);
        float p08 = __expf(sf1[0] - mn0), p09 = __expf(sf1[1] - mn0);
        float p10 = __expf(sf0[2] - mn1), p11 = __expf(sf0[3] - mn1);
        float p18 = __expf(sf1[2] - mn1), p19 = __expf(sf1[3] - mn1);
        float ls0 = p00 + p01 + p08 + p09;
        float ls1 = p10 + p11 + p18 + p19;
        ls0 += __shfl_xor_sync(0xffffffffu, ls0, 1);
        ls0 += __shfl_xor_sync(0xffffffffu, ls0, 2);
        ls1 += __shfl_xor_sync(0xffffffffu, ls1, 1);
        ls1 += __shfl_xor_sync(0xffffffffu, ls1, 2);
        l0r = l0r * a0 + ls0;
        l1r = l1r * a1 + ls1;

        {
            uint32_t h, l;
            char* pr0 = smc + OPH + row0 * PSB + (wh * 16 + 2 * (lane & 3)) * 2;
            char* pr1 = pr0 + 8 * PSB;
            split2(p00, p01, h, l);
            *(uint32_t*)(pr0)                    = h;
            *(uint32_t*)(pr0 + (OPL - OPH))      = l;
            split2(p08, p09, h, l);
            *(uint32_t*)(pr0 + 16)               = h;
            *(uint32_t*)(pr0 + 16 + (OPL - OPH)) = l;
            split2(p10, p11, h, l);
            *(uint32_t*)(pr1)                    = h;
            *(uint32_t*)(pr1 + (OPL - OPH))      = l;
            split2(p18, p19, h, l);
            *(uint32_t*)(pr1 + 16)               = h;
            *(uint32_t*)(pr1 + 16 + (OPL - OPH)) = l;
        }

        #pragma unroll
        for (int nt = 0; nt < 8; nt++) {
            of[nt][0] *= a0; of[nt][1] *= a0;
            of[nt][2] *= a1; of[nt][3] *= a1;
        }
        /* S2 (pair): P rows wr*16..+15 are written/read only by warps (wr,0),(wr,1) */
        BARP(wr);

        /* ---- O += P @ V from buf[p] ---- */
        #pragma unroll
        for (int ks = 0; ks < 2; ks++) {
            uint32_t ph0,ph1,ph2,ph3, pl0,pl1,pl2,pl3;
            ldsm4(pbase + ks * 32,             ph0, ph1, ph2, ph3);
            ldsm4(pbase + (OPL-OPH) + ks * 32, pl0, pl1, pl2, pl3);
            #pragma unroll
            for (int ntp = 0; ntp < 4; ntp++) {
                uint32_t vh0,vh1,vh2,vh3, vl0,vl1,vl2,vl3;
                uint32_t va = vbase + pofs + ks * (16 * TSB) + ntp * 32;
                ldsm4t(va,               vh0, vh1, vh2, vh3);
                ldsm4t(va + (OV0L-OV0H), vl0, vl1, vl2, vl3);
                mma16816(of[ntp*2],   ph0,ph1,ph2,ph3, vh0,vh1);
                mma16816(of[ntp*2],   ph0,ph1,ph2,ph3, vl0,vl1);
                mma16816(of[ntp*2],   pl0,pl1,pl2,pl3, vh0,vh1);
                mma16816(of[ntp*2+1], ph0,ph1,ph2,ph3, vh2,vh3);
                mma16816(of[ntp*2+1], ph0,ph1,ph2,ph3, vl2,vl3);
                mma16816(of[ntp*2+1], pl0,pl1,pl2,pl3, vh2,vh3);
            }
        }
        p ^= 1;
    }

    /* ---- epilogue: write unnormalized partials + (m, l) ---- */
    if ((lane & 3) == 0) {
        sM[wh * 64 + row0]     = l0r;
        sM[wh * 64 + row0 + 8] = l1r;
    }
    BARP(wr);   /* l exchange is pair-local */
    {
        const long slot = ((long)(b * 32 + qb) * NCH + ch);
        float* po = g_po + slot * BM * HD;
        float lj0 = l0r + sM[(wh ^ 1) * 64 + row0];
        float lj1 = l1r + sM[(wh ^ 1) * 64 + row0 + 8];
        if (wh == 0 && (lane & 3) == 0) {
            g_pm[slot * BM + row0]     = m0r;
            g_pm[slot * BM + row0 + 8] = m1r;
            g_pl[slot * BM + row0]     = lj0;
            g_pl[slot * BM + row0 + 8] = lj1;
        }
        float* o0 = po + row0 * HD + wh * 64 + 2 * (lane & 3);
        #pragma unroll
        for (int nt = 0; nt < 8; nt++) {
            *(float2*)(o0 + nt * 8)          = make_float2(of[nt][0], of[nt][1]);
            *(float2*)(o0 + 8 * HD + nt * 8) = make_float2(of[nt][2], of[nt][3]);
        }
    }
}

/* ---------------- kernel 2: combine partials + mean rows ---------------- */
__global__ __launch_bounds__(NTH)
void combine_kernel(const int* __restrict__ LENS, float* __restrict__ OUT)
{
    __shared__ float scr[HD];
    const int b   = blockIdx.y;
    const int qb  = blockIdx.x;
    const int q0  = qb * BM;
    const int len = LENS[b];
    const int tid = threadIdx.x;

    float* ob = OUT + ((long)b * SEQ + q0) * HD;

    int nrows = len - q0; if (nrows > BM) nrows = BM; if (nrows < 0) nrows = 0;
    const int nch  = (len + CHK - 1) / CHK;      /* only touch active chunks */
    const int r    = tid >> 2;
    const int cseg = (tid & 3) * 32;
    if (r < nrows) {
        const long slot0 = (long)(b * 32 + qb) * NCH;
        float mv[NCH], w[NCH];
        float mstar = -INFINITY;
        for (int c = 0; c < nch; c++) {
            mv[c] = g_pm[(slot0 + c) * BM + r];
            mstar = fmaxf(mstar, mv[c]);
        }
        float lsum = 0.f;
        for (int c = 0; c < nch; c++) {
            w[c] = __expf(mv[c] - mstar);
            lsum += w[c] * g_pl[(slot0 + c) * BM + r];
        }
        const float inv = 1.0f / lsum;
        const float* po = g_po + slot0 * BM * HD + (long)r * HD + cseg;
        float* orow = ob + (long)r * HD + cseg;
        #pragma unroll
        for (int j = 0; j < 8; j++) {
            float4 acc = make_float4(0.f, 0.f, 0.f, 0.f);
            for (int c = 0; c < nch; c++) {
                float4 t = *(const float4*)(po + (long)c * BM * HD + 4 * j);
                acc.x += w[c] * t.x; acc.y += w[c] * t.y;
                acc.z += w[c] * t.z; acc.w += w[c] * t.w;
            }
            acc.x *= inv; acc.y *= inv; acc.z *= inv; acc.w *= inv;
            *(float4*)(orow + 4 * j) = acc;
        }
    }

    /* fully-masked rows: uniform softmax -> mean(v[b]) from slice sums */
    if (q0 + BM > len) {
        if (tid < HD) {
            float s = 0.f;
            #pragma unroll
            for (int sl = 0; sl < 8; sl++)
                s += g_msum[(b * 8 + sl) * HD + tid];
            scr[tid] = s * (1.0f / SEQ);
        }
        __syncthreads();
        int rstart = len - q0; if (rstart < 0) rstart = 0;
        for (int idx = tid; idx < (BM - rstart) * HD; idx += NTH) {
            int rr = rstart + (idx >> 7);
            int cc = idx & (HD - 1);
            ob[rr * HD + cc] = scr[cc];
        }
    }
}

extern "C" void kernel_launch(void* const* d_in, const int* in_sizes, int n_in,
                              void* d_out, int out_size)
{
    const float* q    = (const float*)d_in[0];
    const float* k    = (const float*)d_in[1];
    const float* v    = (const float*)d_in[2];
    const int*   lens = (const int*)d_in[3];
    float*       out  = (float*)d_out;

    cudaFuncSetAttribute(attn_part_kernel,
                         cudaFuncAttributeMaxDynamicSharedMemorySize, SMBYTES);

    dim3 g1(SEQ / BM, NB, NCH + 1);
    attn_part_kernel<<<g1, NTH, SMBYTES>>>(q, k, v, lens);

    dim3 g2(SEQ / BM, NB);
    combine_kernel<<<g2, NTH>>>(lens, out);
}